// round 8
// baseline (speedup 1.0000x reference)
#include <cuda_runtime.h>
#include <cuda_fp16.h>

typedef unsigned long long u64;

// Problem constants
#define BB 4
#define CC 32
#define DW 64
#define HH 256
#define WW 256
#define HW 65536

// Scratch (device globals: allocation-free rule). fp16 intermediates.
__device__ __half g_t[BB * DW * HW];    // conv1(LN(inp)) output, 32 MB
__device__ __half g_xsg[BB * CC * HW];  // gate output, 16 MB
__device__ float g_part[BB * CC * 64];  // per-(b,ch,tile) partial sums
__device__ float g_s[BB * CC];          // SCA scale per (b,ch)

// ---- packed fp32x2 helpers (sm_100+) ----
__device__ __forceinline__ u64 pack2(float lo, float hi) {
    u64 r;
    asm("mov.b64 %0, {%1,%2};" : "=l"(r) : "f"(lo), "f"(hi));
    return r;
}
__device__ __forceinline__ float2 unpack2(u64 v) {
    float lo, hi;
    asm("mov.b64 {%0,%1}, %2;" : "=f"(lo), "=f"(hi) : "l"(v));
    return make_float2(lo, hi);
}
__device__ __forceinline__ u64 ffma2(u64 a, u64 b, u64 c) {
    u64 d;
    asm("fma.rn.f32x2 %0, %1, %2, %3;" : "=l"(d) : "l"(a), "l"(b), "l"(c));
    return d;
}
__device__ __forceinline__ u64 add2(u64 a, u64 b) {
    u64 d;
    asm("add.rn.f32x2 %0, %1, %2;" : "=l"(d) : "l"(a), "l"(b));
    return d;
}
__device__ __forceinline__ float hsum2(u64 v) {
    float2 f = unpack2(v);
    return f.x + f.y;
}

// =====================================================================
// K1: per-pixel LayerNorm(channel) + conv1 (32 -> 64), writes g_t (fp16)
// Channel-paired f32x2: xp[c2]=(z[2c2],z[2c2+1]); weight rows read as
// contiguous LDS.64 pairs; one horizontal add per output.
// =====================================================================
__global__ __launch_bounds__(128) void k1(const float* __restrict__ inp,
                                          const float* __restrict__ w1,
                                          const float* __restrict__ b1g,
                                          const float* __restrict__ n1w,
                                          const float* __restrict__ n1b) {
    __shared__ __align__(16) float w1s[64 * 32];  // plain copy, row-major
    __shared__ float snw[32], snb[32], sb64[64];
    int tid = threadIdx.x;
    for (int i = tid; i < 2048; i += 128) w1s[i] = w1[i];
    if (tid < 32) { snw[tid] = n1w[tid]; snb[tid] = n1b[tid]; }
    if (tid < 64) sb64[tid] = b1g[tid];
    __syncthreads();

    int p = blockIdx.x * 128 + tid;
    int b = p >> 16, pix = p & 65535;
    const float* ip = inp + b * CC * HW + pix;

    float x[32];
    float s = 0.f, s2 = 0.f;
#pragma unroll
    for (int c = 0; c < 32; c++) {
        x[c] = ip[c * HW];
        s += x[c];
        s2 += x[c] * x[c];
    }
    float mu = s * (1.f / 32.f);
    float var = s2 * (1.f / 32.f) - mu * mu;
    float rstd = rsqrtf(var + 1e-6f);

    u64 xp[16];
#pragma unroll
    for (int c2 = 0; c2 < 16; c2++) {
        float v0 = (x[2 * c2] - mu) * rstd * snw[2 * c2] + snb[2 * c2];
        float v1 = (x[2 * c2 + 1] - mu) * rstd * snw[2 * c2 + 1] + snb[2 * c2 + 1];
        xp[c2] = pack2(v0, v1);
    }

    __half* op = g_t + b * DW * HW + pix;
#pragma unroll 4
    for (int o = 0; o < 64; o++) {
        u64 acc = pack2(sb64[o], 0.f);
        const u64* wr = reinterpret_cast<const u64*>(&w1s[o * 32]);
#pragma unroll
        for (int c2 = 0; c2 < 16; c2++) acc = ffma2(wr[c2], xp[c2], acc);
        op[o * HW] = __float2half_rn(hsum2(acc));
    }
}

// =====================================================================
// K2: DDF (bilinear-upsampled per-pixel 3x3 filter) + SimpleGate
//     + per-tile partial channel sums for SCA. (frozen; fp16 I/O)
// =====================================================================
__global__ __launch_bounds__(128) void k2(const float* __restrict__ w2g) {
    int tile = blockIdx.x;  // 0..63
    int chp = blockIdx.y;   // 0..31
    int b = blockIdx.z;
    int tyi = tile >> 3, txi = tile & 7;
    int h0 = tyi * 32, w0 = txi * 32;
    const int TSTR = 35;  // smem row stride (conflict-free)

    __shared__ float tin[2][34 * TSTR];
    __shared__ float Wc[2][9][36];  // [ch][tap][6x6 coarse window]
    __shared__ float red[4];

    int tid = threadIdx.x;

#pragma unroll
    for (int cc = 0; cc < 2; cc++) {
        const __half* src = g_t + (b * DW + chp + cc * 32) * HW;
        for (int idx = tid; idx < 34 * 34; idx += 128) {
            int r = idx / 34, c = idx - r * 34;
            int gh = h0 - 1 + r, gw = w0 - 1 + c;
            float v = 0.f;
            if ((unsigned)gh < 256u && (unsigned)gw < 256u)
                v = __half2float(src[gh * 256 + gw]);
            tin[cc][r * TSTR + c] = v;
        }
    }
    {
        int ybase = 4 * tyi - 1, xbase = 4 * txi - 1;
        for (int idx = tid; idx < 648; idx += 128) {
            int cc = idx / 324;
            int rem = idx - cc * 324;
            int t = rem / 36;
            int rc = rem - t * 36;
            int rr = rc / 6, cj = rc - rr * 6;
            int ys = min(max(ybase + rr, 0), 31);
            int xs = min(max(xbase + cj, 0), 31);
            Wc[cc][t][rc] =
                w2g[(((b * 64 + chp + cc * 32) * 9 + t) * 32 + ys) * 32 + xs];
        }
    }
    __syncthreads();

    int row = tid >> 2;        // 0..31
    int seg = (tid & 3) * 8;   // 0,8,16,24
    int h = h0 + row;

    float srcy = (h - 3.5f) * 0.125f;
    float y0f = floorf(srcy);
    float fy = srcy - y0f;
    int y0 = (int)y0f;
    int ybase = 4 * tyi - 1;
    int y0l = max(y0, 0) - ybase;
    int y1l = min(y0 + 1, 31) - ybase;

    int m = 4 * txi + (seg >> 3);
    int xbase = 4 * txi - 1;
    int a0 = max(m - 1, 0) - xbase;
    int a1 = m - xbase;
    int b1i = min(m + 1, 31) - xbase;

    float acc[2][8];
#pragma unroll
    for (int cc = 0; cc < 2; cc++) {
        float ra[10], rb[10], rc[10];
#pragma unroll
        for (int k = 0; k < 10; k++) {
            ra[k] = tin[cc][row * TSTR + seg + k];
            rb[k] = tin[cc][(row + 1) * TSTR + seg + k];
            rc[k] = tin[cc][(row + 2) * TSTR + seg + k];
        }
#pragma unroll
        for (int i = 0; i < 8; i++) acc[cc][i] = 0.f;

#define TAP(RR, T, DX)                                              \
    {                                                               \
        const float* Wp = Wc[cc][T];                                \
        float v0a = Wp[y0l * 6 + a0], v0b = Wp[y1l * 6 + a0];       \
        float v1a = Wp[y0l * 6 + a1], v1b = Wp[y1l * 6 + a1];       \
        float v2a = Wp[y0l * 6 + b1i], v2b = Wp[y1l * 6 + b1i];     \
        float v0 = v0a + fy * (v0b - v0a);                          \
        float v1 = v1a + fy * (v1b - v1a);                          \
        float v2 = v2a + fy * (v2b - v2a);                          \
        float dA = v1 - v0, dB = v2 - v1;                           \
        acc[cc][0] += (v0 + 0.5625f * dA) * RR[0 + DX];             \
        acc[cc][1] += (v0 + 0.6875f * dA) * RR[1 + DX];             \
        acc[cc][2] += (v0 + 0.8125f * dA) * RR[2 + DX];             \
        acc[cc][3] += (v0 + 0.9375f * dA) * RR[3 + DX];             \
        acc[cc][4] += (v1 + 0.0625f * dB) * RR[4 + DX];             \
        acc[cc][5] += (v1 + 0.1875f * dB) * RR[5 + DX];             \
        acc[cc][6] += (v1 + 0.3125f * dB) * RR[6 + DX];             \
        acc[cc][7] += (v1 + 0.4375f * dB) * RR[7 + DX];             \
    }
        TAP(ra, 0, 0) TAP(ra, 1, 1) TAP(ra, 2, 2)
        TAP(rb, 3, 0) TAP(rb, 4, 1) TAP(rb, 5, 2)
        TAP(rc, 6, 0) TAP(rc, 7, 1) TAP(rc, 8, 2)
#undef TAP
    }

    float g[8];
    float tsum = 0.f;
#pragma unroll
    for (int i = 0; i < 8; i++) {
        g[i] = acc[0][i] * acc[1][i];
        tsum += g[i];
    }
    __half2* op =
        (__half2*)(g_xsg + (b * CC + chp) * HW + h * 256 + w0 + seg);
    op[0] = __floats2half2_rn(g[0], g[1]);
    op[1] = __floats2half2_rn(g[2], g[3]);
    op[2] = __floats2half2_rn(g[4], g[5]);
    op[3] = __floats2half2_rn(g[6], g[7]);

#pragma unroll
    for (int off = 16; off; off >>= 1)
        tsum += __shfl_xor_sync(0xffffffffu, tsum, off);
    if ((tid & 31) == 0) red[tid >> 5] = tsum;
    __syncthreads();
    if (tid == 0)
        g_part[(b * CC + chp) * 64 + tile] = red[0] + red[1] + red[2] + red[3];
}

// =====================================================================
// K3: deterministic reduction of partials + SCA 1x1 conv -> g_s
// =====================================================================
__global__ void k3(const float* __restrict__ sw, const float* __restrict__ sbias) {
    __shared__ float mean_sm[128];
    int tid = threadIdx.x;  // 128 = 4 batches x 32 channels
    int b = tid >> 5, c = tid & 31;
    float sum = 0.f;
    for (int t = 0; t < 64; t++) sum += g_part[(b * CC + c) * 64 + t];
    mean_sm[tid] = sum * (1.f / 65536.f);
    __syncthreads();
    float acc = sbias[c];
#pragma unroll
    for (int k = 0; k < 32; k++) acc += sw[c * 32 + k] * mean_sm[b * 32 + k];
    g_s[tid] = acc;
}

// =====================================================================
// K4: x*s -> conv3 -> y = inp + beta*x -> LN2 -> conv4 -> gate -> conv5
//     -> out = y + gamma*z. Channel-paired f32x2 throughout (low regs).
// =====================================================================
__global__ __launch_bounds__(128) void k4(const float* __restrict__ inp,
                                          const float* __restrict__ w3,
                                          const float* __restrict__ b3g,
                                          const float* __restrict__ w4,
                                          const float* __restrict__ b4g,
                                          const float* __restrict__ w5,
                                          const float* __restrict__ b5g,
                                          const float* __restrict__ n2wg,
                                          const float* __restrict__ n2bg,
                                          const float* __restrict__ betag,
                                          const float* __restrict__ gammag,
                                          float* __restrict__ out) {
    __shared__ __align__(16) float w3s[32 * 32];
    __shared__ __align__(16) float w4s[64 * 32];
    __shared__ __align__(16) float w5s[32 * 32];
    __shared__ float sv[32], n2w[32], n2b[32], bet[32], gam[32];
    __shared__ float b3s[32], b4s[64], b5s[32];

    int tid = threadIdx.x;
    int p = blockIdx.x * 128 + tid;
    int b = p >> 16, pix = p & 65535;

    for (int i = tid; i < 1024; i += 128) { w3s[i] = w3[i]; w5s[i] = w5[i]; }
    for (int i = tid; i < 2048; i += 128) w4s[i] = w4[i];
    if (tid < 32) {
        sv[tid] = g_s[b * 32 + tid];
        n2w[tid] = n2wg[tid];
        n2b[tid] = n2bg[tid];
        bet[tid] = betag[tid];
        gam[tid] = gammag[tid];
        b3s[tid] = b3g[tid];
        b5s[tid] = b5g[tid];
    }
    if (tid < 64) b4s[tid] = b4g[tid];
    __syncthreads();

    // x = gate_out * s (fp16 load), channel pairs
    u64 xp[16];
    {
        const __half* xg = g_xsg + b * CC * HW + pix;
#pragma unroll
        for (int c2 = 0; c2 < 16; c2++) {
            float v0 = __half2float(xg[(2 * c2) * HW]) * sv[2 * c2];
            float v1 = __half2float(xg[(2 * c2 + 1) * HW]) * sv[2 * c2 + 1];
            xp[c2] = pack2(v0, v1);
        }
    }

    // ---- conv3 + residual with beta -> yp (channel pairs) ----
    u64 yp[16];
    const float* ip = inp + b * CC * HW + pix;
#pragma unroll 2
    for (int j = 0; j < 16; j++) {
        u64 a0 = pack2(b3s[2 * j], 0.f);
        u64 a1 = pack2(b3s[2 * j + 1], 0.f);
        const u64* wr0 = reinterpret_cast<const u64*>(&w3s[(2 * j) * 32]);
        const u64* wr1 = reinterpret_cast<const u64*>(&w3s[(2 * j + 1) * 32]);
#pragma unroll
        for (int c2 = 0; c2 < 16; c2++) {
            a0 = ffma2(wr0[c2], xp[c2], a0);
            a1 = ffma2(wr1[c2], xp[c2], a1);
        }
        float y0 = ip[(2 * j) * HW] + bet[2 * j] * hsum2(a0);
        float y1 = ip[(2 * j + 1) * HW] + bet[2 * j + 1] * hsum2(a1);
        yp[j] = pack2(y0, y1);
    }

    // ---- LN2 (f32x2 sums) -> zp (reuse xp) ----
    {
        u64 sa = 0ull, qa = 0ull;  // 0x0 == (0.f,0.f)
#pragma unroll
        for (int j = 0; j < 16; j++) {
            sa = add2(sa, yp[j]);
            qa = ffma2(yp[j], yp[j], qa);
        }
        float s = hsum2(sa), s2 = hsum2(qa);
        float mu = s * (1.f / 32.f);
        float var = s2 * (1.f / 32.f) - mu * mu;
        float rstd = rsqrtf(var + 1e-6f);
#pragma unroll
        for (int j = 0; j < 16; j++) {
            float2 f = unpack2(yp[j]);
            float z0 = (f.x - mu) * rstd * n2w[2 * j] + n2b[2 * j];
            float z1 = (f.y - mu) * rstd * n2w[2 * j + 1] + n2b[2 * j + 1];
            xp[j] = pack2(z0, z1);
        }
    }

    // ---- conv4 (64 outs) + gate -> gp (pairs) ----
    u64 gp[16];
#pragma unroll 2
    for (int j = 0; j < 16; j++) {
        u64 aA = pack2(b4s[2 * j], 0.f);
        u64 aB = pack2(b4s[2 * j + 1], 0.f);
        u64 aC = pack2(b4s[2 * j + 32], 0.f);
        u64 aD = pack2(b4s[2 * j + 33], 0.f);
        const u64* wA = reinterpret_cast<const u64*>(&w4s[(2 * j) * 32]);
        const u64* wB = reinterpret_cast<const u64*>(&w4s[(2 * j + 1) * 32]);
        const u64* wC = reinterpret_cast<const u64*>(&w4s[(2 * j + 32) * 32]);
        const u64* wD = reinterpret_cast<const u64*>(&w4s[(2 * j + 33) * 32]);
#pragma unroll
        for (int c2 = 0; c2 < 16; c2++) {
            u64 xv = xp[c2];
            aA = ffma2(wA[c2], xv, aA);
            aB = ffma2(wB[c2], xv, aB);
            aC = ffma2(wC[c2], xv, aC);
            aD = ffma2(wD[c2], xv, aD);
        }
        float g0 = hsum2(aA) * hsum2(aC);
        float g1 = hsum2(aB) * hsum2(aD);
        gp[j] = pack2(g0, g1);
    }

    // ---- conv5 + final residual with gamma ----
    float* op = out + b * CC * HW + pix;
#pragma unroll 2
    for (int j = 0; j < 16; j++) {
        u64 a0 = pack2(b5s[2 * j], 0.f);
        u64 a1 = pack2(b5s[2 * j + 1], 0.f);
        const u64* wr0 = reinterpret_cast<const u64*>(&w5s[(2 * j) * 32]);
        const u64* wr1 = reinterpret_cast<const u64*>(&w5s[(2 * j + 1) * 32]);
#pragma unroll
        for (int c2 = 0; c2 < 16; c2++) {
            a0 = ffma2(wr0[c2], gp[c2], a0);
            a1 = ffma2(wr1[c2], gp[c2], a1);
        }
        float2 f = unpack2(yp[j]);
        op[(2 * j) * HW] = f.x + gam[2 * j] * hsum2(a0);
        op[(2 * j + 1) * HW] = f.y + gam[2 * j + 1] * hsum2(a1);
    }
}

extern "C" void kernel_launch(void* const* d_in, const int* in_sizes, int n_in,
                              void* d_out, int out_size) {
    const float* inp     = (const float*)d_in[0];
    const float* w2      = (const float*)d_in[1];
    const float* conv1_w = (const float*)d_in[2];
    const float* conv1_b = (const float*)d_in[3];
    const float* conv3_w = (const float*)d_in[4];
    const float* conv3_b = (const float*)d_in[5];
    const float* sca_w   = (const float*)d_in[6];
    const float* sca_b   = (const float*)d_in[7];
    const float* conv4_w = (const float*)d_in[8];
    const float* conv4_b = (const float*)d_in[9];
    const float* conv5_w = (const float*)d_in[10];
    const float* conv5_b = (const float*)d_in[11];
    const float* norm1_w = (const float*)d_in[12];
    const float* norm1_b = (const float*)d_in[13];
    const float* norm2_w = (const float*)d_in[14];
    const float* norm2_b = (const float*)d_in[15];
    const float* beta    = (const float*)d_in[16];
    const float* gamma   = (const float*)d_in[17];
    float* out = (float*)d_out;

    k1<<<2048, 128>>>(inp, conv1_w, conv1_b, norm1_w, norm1_b);
    k2<<<dim3(64, 32, 4), 128>>>(w2);
    k3<<<1, 128>>>(sca_w, sca_b);
    k4<<<2048, 128>>>(inp, conv3_w, conv3_b, conv4_w, conv4_b, conv5_w, conv5_b,
                      norm2_w, norm2_b, beta, gamma, out);
}

// round 9
// speedup vs baseline: 1.3479x; 1.3479x over previous
#include <cuda_runtime.h>
#include <cuda_fp16.h>

typedef unsigned long long u64;

// Problem constants
#define BB 4
#define CC 32
#define DW 64
#define HH 256
#define WW 256
#define HW 65536

// Scratch (device globals: allocation-free rule). fp16 intermediates.
__device__ __half g_t[BB * DW * HW];    // conv1(LN(inp)) output, 32 MB
__device__ __half g_xsg[BB * CC * HW];  // gate output, 16 MB
__device__ float g_part[BB * CC * 64];  // per-(b,ch,tile) partial sums
__device__ float g_s[BB * CC];          // SCA scale per (b,ch)

// ---- packed fp32x2 helpers (sm_100+) ----
__device__ __forceinline__ u64 pack2(float lo, float hi) {
    u64 r;
    asm("mov.b64 %0, {%1,%2};" : "=l"(r) : "f"(lo), "f"(hi));
    return r;
}
__device__ __forceinline__ float2 unpack2(u64 v) {
    float lo, hi;
    asm("mov.b64 {%0,%1}, %2;" : "=f"(lo), "=f"(hi) : "l"(v));
    return make_float2(lo, hi);
}
__device__ __forceinline__ u64 ffma2(u64 a, u64 b, u64 c) {
    u64 d;
    asm("fma.rn.f32x2 %0, %1, %2, %3;" : "=l"(d) : "l"(a), "l"(b), "l"(c));
    return d;
}
__device__ __forceinline__ u64 add2(u64 a, u64 b) {
    u64 d;
    asm("add.rn.f32x2 %0, %1, %2;" : "=l"(d) : "l"(a), "l"(b));
    return d;
}
__device__ __forceinline__ float hsum2(u64 v) {
    float2 f = unpack2(v);
    return f.x + f.y;
}
__device__ __forceinline__ float hsum2h(__half2 v) {
    float2 f = __half22float2(v);
    return f.x + f.y;
}

// =====================================================================
// K1: per-pixel LayerNorm(channel) + conv1 (32 -> 64), writes g_t (fp16)
// fp16 channel-paired weights + HFMA2 accumulation; fp32 epilogue.
// =====================================================================
__global__ __launch_bounds__(128) void k1(const float* __restrict__ inp,
                                          const float* __restrict__ w1,
                                          const float* __restrict__ b1g,
                                          const float* __restrict__ n1w,
                                          const float* __restrict__ n1b) {
    __shared__ __align__(16) __half2 w1h[64 * 16];  // [o][c2]
    __shared__ float snw[32], snb[32], sb64[64];
    int tid = threadIdx.x;
    for (int i = tid; i < 1024; i += 128) {
        int o = i >> 4, c2 = i & 15;
        w1h[i] = __floats2half2_rn(w1[o * 32 + 2 * c2], w1[o * 32 + 2 * c2 + 1]);
    }
    if (tid < 32) { snw[tid] = n1w[tid]; snb[tid] = n1b[tid]; }
    if (tid < 64) sb64[tid] = b1g[tid];
    __syncthreads();

    int p = blockIdx.x * 128 + tid;
    int b = p >> 16, pix = p & 65535;
    const float* ip = inp + b * CC * HW + pix;

    float x[32];
    float s = 0.f, s2 = 0.f;
#pragma unroll
    for (int c = 0; c < 32; c++) {
        x[c] = ip[c * HW];
        s += x[c];
        s2 += x[c] * x[c];
    }
    float mu = s * (1.f / 32.f);
    float var = s2 * (1.f / 32.f) - mu * mu;
    float rstd = rsqrtf(var + 1e-6f);

    __half2 xh[16];
#pragma unroll
    for (int c2 = 0; c2 < 16; c2++) {
        float v0 = (x[2 * c2] - mu) * rstd * snw[2 * c2] + snb[2 * c2];
        float v1 = (x[2 * c2 + 1] - mu) * rstd * snw[2 * c2 + 1] + snb[2 * c2 + 1];
        xh[c2] = __floats2half2_rn(v0, v1);
    }

    __half* op = g_t + b * DW * HW + pix;
#pragma unroll 4
    for (int o = 0; o < 64; o++) {
        __half2 acc = __floats2half2_rn(0.f, 0.f);
        const __half2* wr = &w1h[o * 16];
#pragma unroll
        for (int c2 = 0; c2 < 16; c2++) acc = __hfma2(wr[c2], xh[c2], acc);
        op[o * HW] = __float2half_rn(sb64[o] + hsum2h(acc));
    }
}

// =====================================================================
// K2: DDF (bilinear-upsampled per-pixel 3x3 filter) + SimpleGate
//     + per-tile partial channel sums for SCA. (frozen; fp16 I/O)
// =====================================================================
__global__ __launch_bounds__(128) void k2(const float* __restrict__ w2g) {
    int tile = blockIdx.x;  // 0..63
    int chp = blockIdx.y;   // 0..31
    int b = blockIdx.z;
    int tyi = tile >> 3, txi = tile & 7;
    int h0 = tyi * 32, w0 = txi * 32;
    const int TSTR = 35;  // smem row stride (conflict-free)

    __shared__ float tin[2][34 * TSTR];
    __shared__ float Wc[2][9][36];  // [ch][tap][6x6 coarse window]
    __shared__ float red[4];

    int tid = threadIdx.x;

#pragma unroll
    for (int cc = 0; cc < 2; cc++) {
        const __half* src = g_t + (b * DW + chp + cc * 32) * HW;
        for (int idx = tid; idx < 34 * 34; idx += 128) {
            int r = idx / 34, c = idx - r * 34;
            int gh = h0 - 1 + r, gw = w0 - 1 + c;
            float v = 0.f;
            if ((unsigned)gh < 256u && (unsigned)gw < 256u)
                v = __half2float(src[gh * 256 + gw]);
            tin[cc][r * TSTR + c] = v;
        }
    }
    {
        int ybase = 4 * tyi - 1, xbase = 4 * txi - 1;
        for (int idx = tid; idx < 648; idx += 128) {
            int cc = idx / 324;
            int rem = idx - cc * 324;
            int t = rem / 36;
            int rc = rem - t * 36;
            int rr = rc / 6, cj = rc - rr * 6;
            int ys = min(max(ybase + rr, 0), 31);
            int xs = min(max(xbase + cj, 0), 31);
            Wc[cc][t][rc] =
                w2g[(((b * 64 + chp + cc * 32) * 9 + t) * 32 + ys) * 32 + xs];
        }
    }
    __syncthreads();

    int row = tid >> 2;        // 0..31
    int seg = (tid & 3) * 8;   // 0,8,16,24
    int h = h0 + row;

    float srcy = (h - 3.5f) * 0.125f;
    float y0f = floorf(srcy);
    float fy = srcy - y0f;
    int y0 = (int)y0f;
    int ybase = 4 * tyi - 1;
    int y0l = max(y0, 0) - ybase;
    int y1l = min(y0 + 1, 31) - ybase;

    int m = 4 * txi + (seg >> 3);
    int xbase = 4 * txi - 1;
    int a0 = max(m - 1, 0) - xbase;
    int a1 = m - xbase;
    int b1i = min(m + 1, 31) - xbase;

    float acc[2][8];
#pragma unroll
    for (int cc = 0; cc < 2; cc++) {
        float ra[10], rb[10], rc[10];
#pragma unroll
        for (int k = 0; k < 10; k++) {
            ra[k] = tin[cc][row * TSTR + seg + k];
            rb[k] = tin[cc][(row + 1) * TSTR + seg + k];
            rc[k] = tin[cc][(row + 2) * TSTR + seg + k];
        }
#pragma unroll
        for (int i = 0; i < 8; i++) acc[cc][i] = 0.f;

#define TAP(RR, T, DX)                                              \
    {                                                               \
        const float* Wp = Wc[cc][T];                                \
        float v0a = Wp[y0l * 6 + a0], v0b = Wp[y1l * 6 + a0];       \
        float v1a = Wp[y0l * 6 + a1], v1b = Wp[y1l * 6 + a1];       \
        float v2a = Wp[y0l * 6 + b1i], v2b = Wp[y1l * 6 + b1i];     \
        float v0 = v0a + fy * (v0b - v0a);                          \
        float v1 = v1a + fy * (v1b - v1a);                          \
        float v2 = v2a + fy * (v2b - v2a);                          \
        float dA = v1 - v0, dB = v2 - v1;                           \
        acc[cc][0] += (v0 + 0.5625f * dA) * RR[0 + DX];             \
        acc[cc][1] += (v0 + 0.6875f * dA) * RR[1 + DX];             \
        acc[cc][2] += (v0 + 0.8125f * dA) * RR[2 + DX];             \
        acc[cc][3] += (v0 + 0.9375f * dA) * RR[3 + DX];             \
        acc[cc][4] += (v1 + 0.0625f * dB) * RR[4 + DX];             \
        acc[cc][5] += (v1 + 0.1875f * dB) * RR[5 + DX];             \
        acc[cc][6] += (v1 + 0.3125f * dB) * RR[6 + DX];             \
        acc[cc][7] += (v1 + 0.4375f * dB) * RR[7 + DX];             \
    }
        TAP(ra, 0, 0) TAP(ra, 1, 1) TAP(ra, 2, 2)
        TAP(rb, 3, 0) TAP(rb, 4, 1) TAP(rb, 5, 2)
        TAP(rc, 6, 0) TAP(rc, 7, 1) TAP(rc, 8, 2)
#undef TAP
    }

    float g[8];
    float tsum = 0.f;
#pragma unroll
    for (int i = 0; i < 8; i++) {
        g[i] = acc[0][i] * acc[1][i];
        tsum += g[i];
    }
    __half2* op =
        (__half2*)(g_xsg + (b * CC + chp) * HW + h * 256 + w0 + seg);
    op[0] = __floats2half2_rn(g[0], g[1]);
    op[1] = __floats2half2_rn(g[2], g[3]);
    op[2] = __floats2half2_rn(g[4], g[5]);
    op[3] = __floats2half2_rn(g[6], g[7]);

#pragma unroll
    for (int off = 16; off; off >>= 1)
        tsum += __shfl_xor_sync(0xffffffffu, tsum, off);
    if ((tid & 31) == 0) red[tid >> 5] = tsum;
    __syncthreads();
    if (tid == 0)
        g_part[(b * CC + chp) * 64 + tile] = red[0] + red[1] + red[2] + red[3];
}

// =====================================================================
// K3: deterministic reduction of partials + SCA 1x1 conv -> g_s
// =====================================================================
__global__ void k3(const float* __restrict__ sw, const float* __restrict__ sbias) {
    __shared__ float mean_sm[128];
    int tid = threadIdx.x;  // 128 = 4 batches x 32 channels
    int b = tid >> 5, c = tid & 31;
    float sum = 0.f;
    for (int t = 0; t < 64; t++) sum += g_part[(b * CC + c) * 64 + t];
    mean_sm[tid] = sum * (1.f / 65536.f);
    __syncthreads();
    float acc = sbias[c];
#pragma unroll
    for (int k = 0; k < 32; k++) acc += sw[c * 32 + k] * mean_sm[b * 32 + k];
    g_s[tid] = acc;
}

// =====================================================================
// K4: x*s -> conv3 -> y = inp + beta*x -> LN2 -> conv4 -> gate -> conv5
//     -> out = y + gamma*z. fp16 weights + HFMA2 convs; fp32 main path.
// =====================================================================
__global__ __launch_bounds__(128) void k4(const float* __restrict__ inp,
                                          const float* __restrict__ w3,
                                          const float* __restrict__ b3g,
                                          const float* __restrict__ w4,
                                          const float* __restrict__ b4g,
                                          const float* __restrict__ w5,
                                          const float* __restrict__ b5g,
                                          const float* __restrict__ n2wg,
                                          const float* __restrict__ n2bg,
                                          const float* __restrict__ betag,
                                          const float* __restrict__ gammag,
                                          float* __restrict__ out) {
    __shared__ __align__(16) __half2 w3h[32 * 16];  // [o][c2]
    __shared__ __align__(16) __half2 w4h[64 * 16];
    __shared__ __align__(16) __half2 w5h[32 * 16];
    __shared__ float sv[32], n2w[32], n2b[32], bet[32], gam[32];
    __shared__ float b3s[32], b4s[64], b5s[32];

    int tid = threadIdx.x;
    int p = blockIdx.x * 128 + tid;
    int b = p >> 16, pix = p & 65535;

    for (int i = tid; i < 512; i += 128) {
        int o = i >> 4, c2 = i & 15;
        w3h[i] = __floats2half2_rn(w3[o * 32 + 2 * c2], w3[o * 32 + 2 * c2 + 1]);
        w5h[i] = __floats2half2_rn(w5[o * 32 + 2 * c2], w5[o * 32 + 2 * c2 + 1]);
    }
    for (int i = tid; i < 1024; i += 128) {
        int o = i >> 4, c2 = i & 15;
        w4h[i] = __floats2half2_rn(w4[o * 32 + 2 * c2], w4[o * 32 + 2 * c2 + 1]);
    }
    if (tid < 32) {
        sv[tid] = g_s[b * 32 + tid];
        n2w[tid] = n2wg[tid];
        n2b[tid] = n2bg[tid];
        bet[tid] = betag[tid];
        gam[tid] = gammag[tid];
        b3s[tid] = b3g[tid];
        b5s[tid] = b5g[tid];
    }
    if (tid < 64) b4s[tid] = b4g[tid];
    __syncthreads();

    // x = gate_out * s (fp16 load), half2 channel pairs
    __half2 xh[16];
    {
        const __half* xg = g_xsg + b * CC * HW + pix;
#pragma unroll
        for (int c2 = 0; c2 < 16; c2++) {
            float v0 = __half2float(xg[(2 * c2) * HW]) * sv[2 * c2];
            float v1 = __half2float(xg[(2 * c2 + 1) * HW]) * sv[2 * c2 + 1];
            xh[c2] = __floats2half2_rn(v0, v1);
        }
    }

    // ---- conv3 (HFMA2) + residual with beta -> yp (fp32 pairs) ----
    u64 yp[16];
    const float* ip = inp + b * CC * HW + pix;
#pragma unroll 2
    for (int j = 0; j < 16; j++) {
        __half2 a0 = __floats2half2_rn(0.f, 0.f);
        __half2 a1 = a0;
        const __half2* wr0 = &w3h[(2 * j) * 16];
        const __half2* wr1 = &w3h[(2 * j + 1) * 16];
#pragma unroll
        for (int c2 = 0; c2 < 16; c2++) {
            a0 = __hfma2(wr0[c2], xh[c2], a0);
            a1 = __hfma2(wr1[c2], xh[c2], a1);
        }
        float y0 = ip[(2 * j) * HW] + bet[2 * j] * (b3s[2 * j] + hsum2h(a0));
        float y1 =
            ip[(2 * j + 1) * HW] + bet[2 * j + 1] * (b3s[2 * j + 1] + hsum2h(a1));
        yp[j] = pack2(y0, y1);
    }

    // ---- LN2 (f32x2 sums) -> zh (half2) ----
    {
        u64 sa = 0ull, qa = 0ull;
#pragma unroll
        for (int j = 0; j < 16; j++) {
            sa = add2(sa, yp[j]);
            qa = ffma2(yp[j], yp[j], qa);
        }
        float s = hsum2(sa), s2 = hsum2(qa);
        float mu = s * (1.f / 32.f);
        float var = s2 * (1.f / 32.f) - mu * mu;
        float rstd = rsqrtf(var + 1e-6f);
#pragma unroll
        for (int j = 0; j < 16; j++) {
            float2 f = unpack2(yp[j]);
            float z0 = (f.x - mu) * rstd * n2w[2 * j] + n2b[2 * j];
            float z1 = (f.y - mu) * rstd * n2w[2 * j + 1] + n2b[2 * j + 1];
            xh[j] = __floats2half2_rn(z0, z1);
        }
    }

    // ---- conv4 (64 outs, HFMA2) + gate -> gh (half2 pairs) ----
    __half2 gh[16];
#pragma unroll 2
    for (int j = 0; j < 16; j++) {
        __half2 aA = __floats2half2_rn(0.f, 0.f);
        __half2 aB = aA, aC = aA, aD = aA;
        const __half2* wA = &w4h[(2 * j) * 16];
        const __half2* wB = &w4h[(2 * j + 1) * 16];
        const __half2* wC = &w4h[(2 * j + 32) * 16];
        const __half2* wD = &w4h[(2 * j + 33) * 16];
#pragma unroll
        for (int c2 = 0; c2 < 16; c2++) {
            __half2 xv = xh[c2];
            aA = __hfma2(wA[c2], xv, aA);
            aB = __hfma2(wB[c2], xv, aB);
            aC = __hfma2(wC[c2], xv, aC);
            aD = __hfma2(wD[c2], xv, aD);
        }
        float g0 = (b4s[2 * j] + hsum2h(aA)) * (b4s[2 * j + 32] + hsum2h(aC));
        float g1 = (b4s[2 * j + 1] + hsum2h(aB)) * (b4s[2 * j + 33] + hsum2h(aD));
        gh[j] = __floats2half2_rn(g0, g1);
    }

    // ---- conv5 (HFMA2) + final residual with gamma ----
    float* op = out + b * CC * HW + pix;
#pragma unroll 2
    for (int j = 0; j < 16; j++) {
        __half2 a0 = __floats2half2_rn(0.f, 0.f);
        __half2 a1 = a0;
        const __half2* wr0 = &w5h[(2 * j) * 16];
        const __half2* wr1 = &w5h[(2 * j + 1) * 16];
#pragma unroll
        for (int c2 = 0; c2 < 16; c2++) {
            a0 = __hfma2(wr0[c2], gh[c2], a0);
            a1 = __hfma2(wr1[c2], gh[c2], a1);
        }
        float2 f = unpack2(yp[j]);
        op[(2 * j) * HW] = f.x + gam[2 * j] * (b5s[2 * j] + hsum2h(a0));
        op[(2 * j + 1) * HW] =
            f.y + gam[2 * j + 1] * (b5s[2 * j + 1] + hsum2h(a1));
    }
}

extern "C" void kernel_launch(void* const* d_in, const int* in_sizes, int n_in,
                              void* d_out, int out_size) {
    const float* inp     = (const float*)d_in[0];
    const float* w2      = (const float*)d_in[1];
    const float* conv1_w = (const float*)d_in[2];
    const float* conv1_b = (const float*)d_in[3];
    const float* conv3_w = (const float*)d_in[4];
    const float* conv3_b = (const float*)d_in[5];
    const float* sca_w   = (const float*)d_in[6];
    const float* sca_b   = (const float*)d_in[7];
    const float* conv4_w = (const float*)d_in[8];
    const float* conv4_b = (const float*)d_in[9];
    const float* conv5_w = (const float*)d_in[10];
    const float* conv5_b = (const float*)d_in[11];
    const float* norm1_w = (const float*)d_in[12];
    const float* norm1_b = (const float*)d_in[13];
    const float* norm2_w = (const float*)d_in[14];
    const float* norm2_b = (const float*)d_in[15];
    const float* beta    = (const float*)d_in[16];
    const float* gamma   = (const float*)d_in[17];
    float* out = (float*)d_out;

    k1<<<2048, 128>>>(inp, conv1_w, conv1_b, norm1_w, norm1_b);
    k2<<<dim3(64, 32, 4), 128>>>(w2);
    k3<<<1, 128>>>(sca_w, sca_b);
    k4<<<2048, 128>>>(inp, conv3_w, conv3_b, conv4_w, conv4_b, conv5_w, conv5_b,
                      norm2_w, norm2_b, beta, gamma, out);
}

// round 10
// speedup vs baseline: 1.3677x; 1.0147x over previous
#include <cuda_runtime.h>
#include <cuda_fp16.h>

typedef unsigned long long u64;

// Problem constants
#define BB 4
#define CC 32
#define DW 64
#define HH 256
#define WW 256
#define HW 65536

// Scratch (device globals: allocation-free rule). fp16 intermediates.
__device__ __half g_t[BB * DW * HW];    // conv1(LN(inp)) output, 32 MB
__device__ __half g_xsg[BB * CC * HW];  // gate output, 16 MB
__device__ float g_part[BB * CC * 64];  // per-(b,ch,tile) partial sums
__device__ float g_s[BB * CC];          // SCA scale per (b,ch)

// ---- packed fp32x2 helpers (sm_100+) ----
__device__ __forceinline__ u64 pack2(float lo, float hi) {
    u64 r;
    asm("mov.b64 %0, {%1,%2};" : "=l"(r) : "f"(lo), "f"(hi));
    return r;
}
__device__ __forceinline__ float2 unpack2(u64 v) {
    float lo, hi;
    asm("mov.b64 {%0,%1}, %2;" : "=f"(lo), "=f"(hi) : "l"(v));
    return make_float2(lo, hi);
}
__device__ __forceinline__ u64 ffma2(u64 a, u64 b, u64 c) {
    u64 d;
    asm("fma.rn.f32x2 %0, %1, %2, %3;" : "=l"(d) : "l"(a), "l"(b), "l"(c));
    return d;
}
__device__ __forceinline__ u64 add2(u64 a, u64 b) {
    u64 d;
    asm("add.rn.f32x2 %0, %1, %2;" : "=l"(d) : "l"(a), "l"(b));
    return d;
}
__device__ __forceinline__ u64 mul2(u64 a, u64 b) {
    u64 d;
    asm("mul.rn.f32x2 %0, %1, %2;" : "=l"(d) : "l"(a), "l"(b));
    return d;
}
__device__ __forceinline__ float hsum2(u64 v) {
    float2 f = unpack2(v);
    return f.x + f.y;
}
__device__ __forceinline__ float hsum2h(__half2 v) {
    float2 f = __half22float2(v);
    return f.x + f.y;
}

// =====================================================================
// K1: per-pixel LayerNorm(channel) + conv1 (32 -> 64), writes g_t (fp16)
// PIXEL-PAIR version: each thread handles 2 adjacent pixels; one
// channel-paired weight load feeds both pixels' HFMA2 chains.
// =====================================================================
__global__ __launch_bounds__(128) void k1(const float* __restrict__ inp,
                                          const float* __restrict__ w1,
                                          const float* __restrict__ b1g,
                                          const float* __restrict__ n1w,
                                          const float* __restrict__ n1b) {
    __shared__ __align__(16) __half2 w1h[64 * 16];  // [o][c2] channel pairs
    __shared__ float snw[32], snb[32], sb64[64];
    int tid = threadIdx.x;
    for (int i = tid; i < 1024; i += 128) {
        int o = i >> 4, c2 = i & 15;
        w1h[i] = __floats2half2_rn(w1[o * 32 + 2 * c2], w1[o * 32 + 2 * c2 + 1]);
    }
    if (tid < 32) { snw[tid] = n1w[tid]; snb[tid] = n1b[tid]; }
    if (tid < 64) sb64[tid] = b1g[tid];
    __syncthreads();

    int p = blockIdx.x * 256 + tid * 2;  // 2 pixels per thread
    int b = p >> 16, pix = p & 65535;
    const float* ip = inp + b * CC * HW + pix;

    // load 2 pixels per channel; LN stats in f32x2 lanes (lane = pixel)
    u64 xv[32];
    u64 sa = 0ull, qa = 0ull;
#pragma unroll
    for (int c = 0; c < 32; c++) {
        float2 v = *(const float2*)&ip[c * HW];
        u64 t = pack2(v.x, v.y);
        xv[c] = t;
        sa = add2(sa, t);
        qa = ffma2(t, t, qa);
    }
    u64 nmu = mul2(sa, pack2(-1.f / 32.f, -1.f / 32.f));  // -mu per pixel
    float2 qf = unpack2(qa);
    float2 nm = unpack2(nmu);
    float var0 = qf.x * (1.f / 32.f) - nm.x * nm.x;
    float var1 = qf.y * (1.f / 32.f) - nm.y * nm.y;
    u64 rs2 = pack2(rsqrtf(var0 + 1e-6f), rsqrtf(var1 + 1e-6f));

    // z per channel (both pixels), repack to channel-paired half2 per pixel
    __half2 xh0[16], xh1[16];
#pragma unroll
    for (int c2 = 0; c2 < 16; c2++) {
        int ca = 2 * c2, cb = 2 * c2 + 1;
        u64 ta = mul2(add2(xv[ca], nmu), rs2);
        u64 tb = mul2(add2(xv[cb], nmu), rs2);
        u64 za = ffma2(ta, pack2(snw[ca], snw[ca]), pack2(snb[ca], snb[ca]));
        u64 zb = ffma2(tb, pack2(snw[cb], snw[cb]), pack2(snb[cb], snb[cb]));
        float2 fa = unpack2(za), fb = unpack2(zb);
        xh0[c2] = __floats2half2_rn(fa.x, fb.x);  // pixel 0, channels (ca,cb)
        xh1[c2] = __floats2half2_rn(fa.y, fb.y);  // pixel 1
    }

    __half* op = g_t + b * DW * HW + pix;
#pragma unroll 4
    for (int o = 0; o < 64; o++) {
        __half2 a0 = __floats2half2_rn(0.f, 0.f);
        __half2 a1 = a0;
        const __half2* wr = &w1h[o * 16];
#pragma unroll
        for (int c2 = 0; c2 < 16; c2++) {
            __half2 w = wr[c2];
            a0 = __hfma2(w, xh0[c2], a0);
            a1 = __hfma2(w, xh1[c2], a1);
        }
        float r0 = sb64[o] + hsum2h(a0);
        float r1 = sb64[o] + hsum2h(a1);
        *(__half2*)&op[o * HW] = __floats2half2_rn(r0, r1);
    }
}

// =====================================================================
// K2: DDF (bilinear-upsampled per-pixel 3x3 filter) + SimpleGate
//     + per-tile partial channel sums for SCA. (frozen; fp16 I/O)
// =====================================================================
__global__ __launch_bounds__(128) void k2(const float* __restrict__ w2g) {
    int tile = blockIdx.x;  // 0..63
    int chp = blockIdx.y;   // 0..31
    int b = blockIdx.z;
    int tyi = tile >> 3, txi = tile & 7;
    int h0 = tyi * 32, w0 = txi * 32;
    const int TSTR = 35;  // smem row stride (conflict-free)

    __shared__ float tin[2][34 * TSTR];
    __shared__ float Wc[2][9][36];  // [ch][tap][6x6 coarse window]
    __shared__ float red[4];

    int tid = threadIdx.x;

#pragma unroll
    for (int cc = 0; cc < 2; cc++) {
        const __half* src = g_t + (b * DW + chp + cc * 32) * HW;
        for (int idx = tid; idx < 34 * 34; idx += 128) {
            int r = idx / 34, c = idx - r * 34;
            int gh = h0 - 1 + r, gw = w0 - 1 + c;
            float v = 0.f;
            if ((unsigned)gh < 256u && (unsigned)gw < 256u)
                v = __half2float(src[gh * 256 + gw]);
            tin[cc][r * TSTR + c] = v;
        }
    }
    {
        int ybase = 4 * tyi - 1, xbase = 4 * txi - 1;
        for (int idx = tid; idx < 648; idx += 128) {
            int cc = idx / 324;
            int rem = idx - cc * 324;
            int t = rem / 36;
            int rc = rem - t * 36;
            int rr = rc / 6, cj = rc - rr * 6;
            int ys = min(max(ybase + rr, 0), 31);
            int xs = min(max(xbase + cj, 0), 31);
            Wc[cc][t][rc] =
                w2g[(((b * 64 + chp + cc * 32) * 9 + t) * 32 + ys) * 32 + xs];
        }
    }
    __syncthreads();

    int row = tid >> 2;        // 0..31
    int seg = (tid & 3) * 8;   // 0,8,16,24
    int h = h0 + row;

    float srcy = (h - 3.5f) * 0.125f;
    float y0f = floorf(srcy);
    float fy = srcy - y0f;
    int y0 = (int)y0f;
    int ybase = 4 * tyi - 1;
    int y0l = max(y0, 0) - ybase;
    int y1l = min(y0 + 1, 31) - ybase;

    int m = 4 * txi + (seg >> 3);
    int xbase = 4 * txi - 1;
    int a0 = max(m - 1, 0) - xbase;
    int a1 = m - xbase;
    int b1i = min(m + 1, 31) - xbase;

    float acc[2][8];
#pragma unroll
    for (int cc = 0; cc < 2; cc++) {
        float ra[10], rb[10], rc[10];
#pragma unroll
        for (int k = 0; k < 10; k++) {
            ra[k] = tin[cc][row * TSTR + seg + k];
            rb[k] = tin[cc][(row + 1) * TSTR + seg + k];
            rc[k] = tin[cc][(row + 2) * TSTR + seg + k];
        }
#pragma unroll
        for (int i = 0; i < 8; i++) acc[cc][i] = 0.f;

#define TAP(RR, T, DX)                                              \
    {                                                               \
        const float* Wp = Wc[cc][T];                                \
        float v0a = Wp[y0l * 6 + a0], v0b = Wp[y1l * 6 + a0];       \
        float v1a = Wp[y0l * 6 + a1], v1b = Wp[y1l * 6 + a1];       \
        float v2a = Wp[y0l * 6 + b1i], v2b = Wp[y1l * 6 + b1i];     \
        float v0 = v0a + fy * (v0b - v0a);                          \
        float v1 = v1a + fy * (v1b - v1a);                          \
        float v2 = v2a + fy * (v2b - v2a);                          \
        float dA = v1 - v0, dB = v2 - v1;                           \
        acc[cc][0] += (v0 + 0.5625f * dA) * RR[0 + DX];             \
        acc[cc][1] += (v0 + 0.6875f * dA) * RR[1 + DX];             \
        acc[cc][2] += (v0 + 0.8125f * dA) * RR[2 + DX];             \
        acc[cc][3] += (v0 + 0.9375f * dA) * RR[3 + DX];             \
        acc[cc][4] += (v1 + 0.0625f * dB) * RR[4 + DX];             \
        acc[cc][5] += (v1 + 0.1875f * dB) * RR[5 + DX];             \
        acc[cc][6] += (v1 + 0.3125f * dB) * RR[6 + DX];             \
        acc[cc][7] += (v1 + 0.4375f * dB) * RR[7 + DX];             \
    }
        TAP(ra, 0, 0) TAP(ra, 1, 1) TAP(ra, 2, 2)
        TAP(rb, 3, 0) TAP(rb, 4, 1) TAP(rb, 5, 2)
        TAP(rc, 6, 0) TAP(rc, 7, 1) TAP(rc, 8, 2)
#undef TAP
    }

    float g[8];
    float tsum = 0.f;
#pragma unroll
    for (int i = 0; i < 8; i++) {
        g[i] = acc[0][i] * acc[1][i];
        tsum += g[i];
    }
    __half2* op =
        (__half2*)(g_xsg + (b * CC + chp) * HW + h * 256 + w0 + seg);
    op[0] = __floats2half2_rn(g[0], g[1]);
    op[1] = __floats2half2_rn(g[2], g[3]);
    op[2] = __floats2half2_rn(g[4], g[5]);
    op[3] = __floats2half2_rn(g[6], g[7]);

#pragma unroll
    for (int off = 16; off; off >>= 1)
        tsum += __shfl_xor_sync(0xffffffffu, tsum, off);
    if ((tid & 31) == 0) red[tid >> 5] = tsum;
    __syncthreads();
    if (tid == 0)
        g_part[(b * CC + chp) * 64 + tile] = red[0] + red[1] + red[2] + red[3];
}

// =====================================================================
// K3: deterministic reduction of partials + SCA 1x1 conv -> g_s
// =====================================================================
__global__ void k3(const float* __restrict__ sw, const float* __restrict__ sbias) {
    __shared__ float mean_sm[128];
    int tid = threadIdx.x;  // 128 = 4 batches x 32 channels
    int b = tid >> 5, c = tid & 31;
    float sum = 0.f;
    for (int t = 0; t < 64; t++) sum += g_part[(b * CC + c) * 64 + t];
    mean_sm[tid] = sum * (1.f / 65536.f);
    __syncthreads();
    float acc = sbias[c];
#pragma unroll
    for (int k = 0; k < 32; k++) acc += sw[c * 32 + k] * mean_sm[b * 32 + k];
    g_s[tid] = acc;
}

// =====================================================================
// K4: x*s -> conv3 -> y = inp + beta*x -> LN2 -> conv4 -> gate -> conv5
//     -> out = y + gamma*z. fp16 weights + HFMA2 convs; fp32 main path.
// (frozen from R9 — 57.3 us)
// =====================================================================
__global__ __launch_bounds__(128) void k4(const float* __restrict__ inp,
                                          const float* __restrict__ w3,
                                          const float* __restrict__ b3g,
                                          const float* __restrict__ w4,
                                          const float* __restrict__ b4g,
                                          const float* __restrict__ w5,
                                          const float* __restrict__ b5g,
                                          const float* __restrict__ n2wg,
                                          const float* __restrict__ n2bg,
                                          const float* __restrict__ betag,
                                          const float* __restrict__ gammag,
                                          float* __restrict__ out) {
    __shared__ __align__(16) __half2 w3h[32 * 16];  // [o][c2]
    __shared__ __align__(16) __half2 w4h[64 * 16];
    __shared__ __align__(16) __half2 w5h[32 * 16];
    __shared__ float sv[32], n2w[32], n2b[32], bet[32], gam[32];
    __shared__ float b3s[32], b4s[64], b5s[32];

    int tid = threadIdx.x;
    int p = blockIdx.x * 128 + tid;
    int b = p >> 16, pix = p & 65535;

    for (int i = tid; i < 512; i += 128) {
        int o = i >> 4, c2 = i & 15;
        w3h[i] = __floats2half2_rn(w3[o * 32 + 2 * c2], w3[o * 32 + 2 * c2 + 1]);
        w5h[i] = __floats2half2_rn(w5[o * 32 + 2 * c2], w5[o * 32 + 2 * c2 + 1]);
    }
    for (int i = tid; i < 1024; i += 128) {
        int o = i >> 4, c2 = i & 15;
        w4h[i] = __floats2half2_rn(w4[o * 32 + 2 * c2], w4[o * 32 + 2 * c2 + 1]);
    }
    if (tid < 32) {
        sv[tid] = g_s[b * 32 + tid];
        n2w[tid] = n2wg[tid];
        n2b[tid] = n2bg[tid];
        bet[tid] = betag[tid];
        gam[tid] = gammag[tid];
        b3s[tid] = b3g[tid];
        b5s[tid] = b5g[tid];
    }
    if (tid < 64) b4s[tid] = b4g[tid];
    __syncthreads();

    // x = gate_out * s (fp16 load), half2 channel pairs
    __half2 xh[16];
    {
        const __half* xg = g_xsg + b * CC * HW + pix;
#pragma unroll
        for (int c2 = 0; c2 < 16; c2++) {
            float v0 = __half2float(xg[(2 * c2) * HW]) * sv[2 * c2];
            float v1 = __half2float(xg[(2 * c2 + 1) * HW]) * sv[2 * c2 + 1];
            xh[c2] = __floats2half2_rn(v0, v1);
        }
    }

    // ---- conv3 (HFMA2) + residual with beta -> yp (fp32 pairs) ----
    u64 yp[16];
    const float* ip = inp + b * CC * HW + pix;
#pragma unroll 2
    for (int j = 0; j < 16; j++) {
        __half2 a0 = __floats2half2_rn(0.f, 0.f);
        __half2 a1 = a0;
        const __half2* wr0 = &w3h[(2 * j) * 16];
        const __half2* wr1 = &w3h[(2 * j + 1) * 16];
#pragma unroll
        for (int c2 = 0; c2 < 16; c2++) {
            a0 = __hfma2(wr0[c2], xh[c2], a0);
            a1 = __hfma2(wr1[c2], xh[c2], a1);
        }
        float y0 = ip[(2 * j) * HW] + bet[2 * j] * (b3s[2 * j] + hsum2h(a0));
        float y1 =
            ip[(2 * j + 1) * HW] + bet[2 * j + 1] * (b3s[2 * j + 1] + hsum2h(a1));
        yp[j] = pack2(y0, y1);
    }

    // ---- LN2 (f32x2 sums) -> zh (half2) ----
    {
        u64 sa = 0ull, qa = 0ull;
#pragma unroll
        for (int j = 0; j < 16; j++) {
            sa = add2(sa, yp[j]);
            qa = ffma2(yp[j], yp[j], qa);
        }
        float s = hsum2(sa), s2 = hsum2(qa);
        float mu = s * (1.f / 32.f);
        float var = s2 * (1.f / 32.f) - mu * mu;
        float rstd = rsqrtf(var + 1e-6f);
#pragma unroll
        for (int j = 0; j < 16; j++) {
            float2 f = unpack2(yp[j]);
            float z0 = (f.x - mu) * rstd * n2w[2 * j] + n2b[2 * j];
            float z1 = (f.y - mu) * rstd * n2w[2 * j + 1] + n2b[2 * j + 1];
            xh[j] = __floats2half2_rn(z0, z1);
        }
    }

    // ---- conv4 (64 outs, HFMA2) + gate -> gh (half2 pairs) ----
    __half2 gh[16];
#pragma unroll 2
    for (int j = 0; j < 16; j++) {
        __half2 aA = __floats2half2_rn(0.f, 0.f);
        __half2 aB = aA, aC = aA, aD = aA;
        const __half2* wA = &w4h[(2 * j) * 16];
        const __half2* wB = &w4h[(2 * j + 1) * 16];
        const __half2* wC = &w4h[(2 * j + 32) * 16];
        const __half2* wD = &w4h[(2 * j + 33) * 16];
#pragma unroll
        for (int c2 = 0; c2 < 16; c2++) {
            __half2 xv = xh[c2];
            aA = __hfma2(wA[c2], xv, aA);
            aB = __hfma2(wB[c2], xv, aB);
            aC = __hfma2(wC[c2], xv, aC);
            aD = __hfma2(wD[c2], xv, aD);
        }
        float g0 = (b4s[2 * j] + hsum2h(aA)) * (b4s[2 * j + 32] + hsum2h(aC));
        float g1 = (b4s[2 * j + 1] + hsum2h(aB)) * (b4s[2 * j + 33] + hsum2h(aD));
        gh[j] = __floats2half2_rn(g0, g1);
    }

    // ---- conv5 (HFMA2) + final residual with gamma ----
    float* op = out + b * CC * HW + pix;
#pragma unroll 2
    for (int j = 0; j < 16; j++) {
        __half2 a0 = __floats2half2_rn(0.f, 0.f);
        __half2 a1 = a0;
        const __half2* wr0 = &w5h[(2 * j) * 16];
        const __half2* wr1 = &w5h[(2 * j + 1) * 16];
#pragma unroll
        for (int c2 = 0; c2 < 16; c2++) {
            a0 = __hfma2(wr0[c2], gh[c2], a0);
            a1 = __hfma2(wr1[c2], gh[c2], a1);
        }
        float2 f = unpack2(yp[j]);
        op[(2 * j) * HW] = f.x + gam[2 * j] * (b5s[2 * j] + hsum2h(a0));
        op[(2 * j + 1) * HW] =
            f.y + gam[2 * j + 1] * (b5s[2 * j + 1] + hsum2h(a1));
    }
}

extern "C" void kernel_launch(void* const* d_in, const int* in_sizes, int n_in,
                              void* d_out, int out_size) {
    const float* inp     = (const float*)d_in[0];
    const float* w2      = (const float*)d_in[1];
    const float* conv1_w = (const float*)d_in[2];
    const float* conv1_b = (const float*)d_in[3];
    const float* conv3_w = (const float*)d_in[4];
    const float* conv3_b = (const float*)d_in[5];
    const float* sca_w   = (const float*)d_in[6];
    const float* sca_b   = (const float*)d_in[7];
    const float* conv4_w = (const float*)d_in[8];
    const float* conv4_b = (const float*)d_in[9];
    const float* conv5_w = (const float*)d_in[10];
    const float* conv5_b = (const float*)d_in[11];
    const float* norm1_w = (const float*)d_in[12];
    const float* norm1_b = (const float*)d_in[13];
    const float* norm2_w = (const float*)d_in[14];
    const float* norm2_b = (const float*)d_in[15];
    const float* beta    = (const float*)d_in[16];
    const float* gamma   = (const float*)d_in[17];
    float* out = (float*)d_out;

    k1<<<1024, 128>>>(inp, conv1_w, conv1_b, norm1_w, norm1_b);
    k2<<<dim3(64, 32, 4), 128>>>(w2);
    k3<<<1, 128>>>(sca_w, sca_b);
    k4<<<2048, 128>>>(inp, conv3_w, conv3_b, conv4_w, conv4_b, conv5_w, conv5_b,
                      norm2_w, norm2_b, beta, gamma, out);
}

// round 11
// speedup vs baseline: 1.5718x; 1.1493x over previous
#include <cuda_runtime.h>
#include <cuda_fp16.h>

typedef unsigned long long u64;

// Problem constants
#define BB 4
#define CC 32
#define DW 64
#define HH 256
#define WW 256
#define HW 65536

// Scratch (device globals: allocation-free rule). fp16 intermediates.
__device__ __half g_t[BB * DW * HW];    // conv1(LN(inp)) output, 32 MB
__device__ __half g_xsg[BB * CC * HW];  // gate output, 16 MB
__device__ float g_part[BB * CC * 64];  // per-(b,ch,tile) partial sums
__device__ float g_s[BB * CC];          // SCA scale per (b,ch)

// ---- packed fp32x2 helpers (sm_100+) ----
__device__ __forceinline__ u64 pack2(float lo, float hi) {
    u64 r;
    asm("mov.b64 %0, {%1,%2};" : "=l"(r) : "f"(lo), "f"(hi));
    return r;
}
__device__ __forceinline__ float2 unpack2(u64 v) {
    float lo, hi;
    asm("mov.b64 {%0,%1}, %2;" : "=f"(lo), "=f"(hi) : "l"(v));
    return make_float2(lo, hi);
}
__device__ __forceinline__ u64 ffma2(u64 a, u64 b, u64 c) {
    u64 d;
    asm("fma.rn.f32x2 %0, %1, %2, %3;" : "=l"(d) : "l"(a), "l"(b), "l"(c));
    return d;
}
__device__ __forceinline__ u64 add2(u64 a, u64 b) {
    u64 d;
    asm("add.rn.f32x2 %0, %1, %2;" : "=l"(d) : "l"(a), "l"(b));
    return d;
}
__device__ __forceinline__ u64 mul2(u64 a, u64 b) {
    u64 d;
    asm("mul.rn.f32x2 %0, %1, %2;" : "=l"(d) : "l"(a), "l"(b));
    return d;
}
__device__ __forceinline__ float hsum2(u64 v) {
    float2 f = unpack2(v);
    return f.x + f.y;
}
__device__ __forceinline__ float hsum2h(__half2 v) {
    float2 f = __half22float2(v);
    return f.x + f.y;
}

// =====================================================================
// K1: per-pixel LayerNorm(channel) + conv1 (32 -> 64), writes g_t (fp16)
// PIXEL-PAIR version (frozen from R10).
// =====================================================================
__global__ __launch_bounds__(128) void k1(const float* __restrict__ inp,
                                          const float* __restrict__ w1,
                                          const float* __restrict__ b1g,
                                          const float* __restrict__ n1w,
                                          const float* __restrict__ n1b) {
    __shared__ __align__(16) __half2 w1h[64 * 16];  // [o][c2] channel pairs
    __shared__ float snw[32], snb[32], sb64[64];
    int tid = threadIdx.x;
    for (int i = tid; i < 1024; i += 128) {
        int o = i >> 4, c2 = i & 15;
        w1h[i] = __floats2half2_rn(w1[o * 32 + 2 * c2], w1[o * 32 + 2 * c2 + 1]);
    }
    if (tid < 32) { snw[tid] = n1w[tid]; snb[tid] = n1b[tid]; }
    if (tid < 64) sb64[tid] = b1g[tid];
    __syncthreads();

    int p = blockIdx.x * 256 + tid * 2;  // 2 pixels per thread
    int b = p >> 16, pix = p & 65535;
    const float* ip = inp + b * CC * HW + pix;

    u64 xv[32];
    u64 sa = 0ull, qa = 0ull;
#pragma unroll
    for (int c = 0; c < 32; c++) {
        float2 v = *(const float2*)&ip[c * HW];
        u64 t = pack2(v.x, v.y);
        xv[c] = t;
        sa = add2(sa, t);
        qa = ffma2(t, t, qa);
    }
    u64 nmu = mul2(sa, pack2(-1.f / 32.f, -1.f / 32.f));
    float2 qf = unpack2(qa);
    float2 nm = unpack2(nmu);
    float var0 = qf.x * (1.f / 32.f) - nm.x * nm.x;
    float var1 = qf.y * (1.f / 32.f) - nm.y * nm.y;
    u64 rs2 = pack2(rsqrtf(var0 + 1e-6f), rsqrtf(var1 + 1e-6f));

    __half2 xh0[16], xh1[16];
#pragma unroll
    for (int c2 = 0; c2 < 16; c2++) {
        int ca = 2 * c2, cb = 2 * c2 + 1;
        u64 ta = mul2(add2(xv[ca], nmu), rs2);
        u64 tb = mul2(add2(xv[cb], nmu), rs2);
        u64 za = ffma2(ta, pack2(snw[ca], snw[ca]), pack2(snb[ca], snb[ca]));
        u64 zb = ffma2(tb, pack2(snw[cb], snw[cb]), pack2(snb[cb], snb[cb]));
        float2 fa = unpack2(za), fb = unpack2(zb);
        xh0[c2] = __floats2half2_rn(fa.x, fb.x);
        xh1[c2] = __floats2half2_rn(fa.y, fb.y);
    }

    __half* op = g_t + b * DW * HW + pix;
#pragma unroll 4
    for (int o = 0; o < 64; o++) {
        __half2 a0 = __floats2half2_rn(0.f, 0.f);
        __half2 a1 = a0;
        const __half2* wr = &w1h[o * 16];
#pragma unroll
        for (int c2 = 0; c2 < 16; c2++) {
            __half2 w = wr[c2];
            a0 = __hfma2(w, xh0[c2], a0);
            a1 = __hfma2(w, xh1[c2], a1);
        }
        float r0 = sb64[o] + hsum2h(a0);
        float r1 = sb64[o] + hsum2h(a1);
        *(__half2*)&op[o * HW] = __floats2half2_rn(r0, r1);
    }
}

// =====================================================================
// K2: DDF + SimpleGate + SCA partials — HALF2-LANE version: both channels
// of the pair ride in fp16 SIMD lanes; taps in __hfma2.
// =====================================================================
__global__ __launch_bounds__(128) void k2(const float* __restrict__ w2g) {
    int tile = blockIdx.x;  // 0..63
    int chp = blockIdx.y;   // 0..31
    int b = blockIdx.z;
    int tyi = tile >> 3, txi = tile & 7;
    int h0 = tyi * 32, w0 = txi * 32;
    const int TSTR = 35;  // smem row stride in half2 elems

    __shared__ __align__(16) __half2 tin[34 * TSTR];  // (ch0, ch1) per px
    __shared__ __align__(16) __half2 Wc[9][36];       // (ch0, ch1) per wgt
    __shared__ float red[4];

    int tid = threadIdx.x;

    // stage conv1-output tile + 1-px zero halo, both channels packed
    {
        const __half* src0 = g_t + (b * DW + chp) * HW;
        const __half* src1 = g_t + (b * DW + chp + 32) * HW;
        __half hz = __float2half_rn(0.f);
        for (int idx = tid; idx < 34 * 34; idx += 128) {
            int r = idx / 34, c = idx - r * 34;
            int gh = h0 - 1 + r, gw = w0 - 1 + c;
            __half v0 = hz, v1 = hz;
            if ((unsigned)gh < 256u && (unsigned)gw < 256u) {
                int off = gh * 256 + gw;
                v0 = src0[off];
                v1 = src1[off];
            }
            tin[r * TSTR + c] = __halves2half2(v0, v1);
        }
    }
    // stage 6x6 coarse-weight windows, both channels packed
    {
        int ybase = 4 * tyi - 1, xbase = 4 * txi - 1;
        for (int idx = tid; idx < 324; idx += 128) {
            int t = idx / 36;
            int rc = idx - t * 36;
            int rr = rc / 6, cj = rc - rr * 6;
            int ys = min(max(ybase + rr, 0), 31);
            int xs = min(max(xbase + cj, 0), 31);
            float wv0 = w2g[(((b * 64 + chp) * 9 + t) * 32 + ys) * 32 + xs];
            float wv1 = w2g[(((b * 64 + chp + 32) * 9 + t) * 32 + ys) * 32 + xs];
            Wc[t][rc] = __floats2half2_rn(wv0, wv1);
        }
    }
    __syncthreads();

    int row = tid >> 2;        // 0..31
    int seg = (tid & 3) * 8;   // 0,8,16,24
    int h = h0 + row;

    float srcy = (h - 3.5f) * 0.125f;
    float y0f = floorf(srcy);
    float fy = srcy - y0f;
    int y0 = (int)y0f;
    int ybase = 4 * tyi - 1;
    int y0l = max(y0, 0) - ybase;
    int y1l = min(y0 + 1, 31) - ybase;

    int m = 4 * txi + (seg >> 3);
    int xbase = 4 * txi - 1;
    int a0 = max(m - 1, 0) - xbase;
    int a1 = m - xbase;
    int b1i = min(m + 1, 31) - xbase;

    __half2 fy2 = __float2half2_rn(fy);
    const __half2 K0 = __float2half2_rn(0.5625f);
    const __half2 K1 = __float2half2_rn(0.6875f);
    const __half2 K2 = __float2half2_rn(0.8125f);
    const __half2 K3 = __float2half2_rn(0.9375f);
    const __half2 K4 = __float2half2_rn(0.0625f);
    const __half2 K5 = __float2half2_rn(0.1875f);
    const __half2 K6 = __float2half2_rn(0.3125f);
    const __half2 K7 = __float2half2_rn(0.4375f);

    // row runs (10 half2 each)
    __half2 ra[10], rb[10], rcr[10];
#pragma unroll
    for (int k = 0; k < 10; k++) {
        ra[k] = tin[row * TSTR + seg + k];
        rb[k] = tin[(row + 1) * TSTR + seg + k];
        rcr[k] = tin[(row + 2) * TSTR + seg + k];
    }

    __half2 acc[8];
#pragma unroll
    for (int i = 0; i < 8; i++) acc[i] = __floats2half2_rn(0.f, 0.f);

#define TAP(RR, T, DX)                                                    \
    {                                                                     \
        const __half2* Wp = Wc[T];                                        \
        __half2 v0a = Wp[y0l * 6 + a0], v0b = Wp[y1l * 6 + a0];           \
        __half2 v1a = Wp[y0l * 6 + a1], v1b = Wp[y1l * 6 + a1];           \
        __half2 v2a = Wp[y0l * 6 + b1i], v2b = Wp[y1l * 6 + b1i];         \
        __half2 v0 = __hfma2(fy2, __hsub2(v0b, v0a), v0a);                \
        __half2 v1 = __hfma2(fy2, __hsub2(v1b, v1a), v1a);                \
        __half2 v2 = __hfma2(fy2, __hsub2(v2b, v2a), v2a);                \
        __half2 dA = __hsub2(v1, v0), dB = __hsub2(v2, v1);               \
        acc[0] = __hfma2(__hfma2(K0, dA, v0), RR[0 + DX], acc[0]);        \
        acc[1] = __hfma2(__hfma2(K1, dA, v0), RR[1 + DX], acc[1]);        \
        acc[2] = __hfma2(__hfma2(K2, dA, v0), RR[2 + DX], acc[2]);        \
        acc[3] = __hfma2(__hfma2(K3, dA, v0), RR[3 + DX], acc[3]);        \
        acc[4] = __hfma2(__hfma2(K4, dB, v1), RR[4 + DX], acc[4]);        \
        acc[5] = __hfma2(__hfma2(K5, dB, v1), RR[5 + DX], acc[5]);        \
        acc[6] = __hfma2(__hfma2(K6, dB, v1), RR[6 + DX], acc[6]);        \
        acc[7] = __hfma2(__hfma2(K7, dB, v1), RR[7 + DX], acc[7]);        \
    }
    TAP(ra, 0, 0) TAP(ra, 1, 1) TAP(ra, 2, 2)
    TAP(rb, 3, 0) TAP(rb, 4, 1) TAP(rb, 5, 2)
    TAP(rcr, 6, 0) TAP(rcr, 7, 1) TAP(rcr, 8, 2)
#undef TAP

    // SimpleGate (lane0 * lane1) + fp16 store + tile-sum
    float g[8];
    float tsum = 0.f;
#pragma unroll
    for (int i = 0; i < 8; i++) {
        float2 f = __half22float2(acc[i]);
        g[i] = f.x * f.y;
        tsum += g[i];
    }
    __half2* op =
        (__half2*)(g_xsg + (b * CC + chp) * HW + h * 256 + w0 + seg);
    op[0] = __floats2half2_rn(g[0], g[1]);
    op[1] = __floats2half2_rn(g[2], g[3]);
    op[2] = __floats2half2_rn(g[4], g[5]);
    op[3] = __floats2half2_rn(g[6], g[7]);

#pragma unroll
    for (int off = 16; off; off >>= 1)
        tsum += __shfl_xor_sync(0xffffffffu, tsum, off);
    if ((tid & 31) == 0) red[tid >> 5] = tsum;
    __syncthreads();
    if (tid == 0)
        g_part[(b * CC + chp) * 64 + tile] = red[0] + red[1] + red[2] + red[3];
}

// =====================================================================
// K3: deterministic reduction of partials + SCA 1x1 conv -> g_s
// =====================================================================
__global__ void k3(const float* __restrict__ sw, const float* __restrict__ sbias) {
    __shared__ float mean_sm[128];
    int tid = threadIdx.x;  // 128 = 4 batches x 32 channels
    int b = tid >> 5, c = tid & 31;
    float sum = 0.f;
    for (int t = 0; t < 64; t++) sum += g_part[(b * CC + c) * 64 + t];
    mean_sm[tid] = sum * (1.f / 65536.f);
    __syncthreads();
    float acc = sbias[c];
#pragma unroll
    for (int k = 0; k < 32; k++) acc += sw[c * 32 + k] * mean_sm[b * 32 + k];
    g_s[tid] = acc;
}

// =====================================================================
// K4: x*s -> conv3 -> y = inp + beta*x -> LN2 -> conv4 -> gate -> conv5
//     -> out = y + gamma*z. (frozen from R9 — 57-58 us)
// =====================================================================
__global__ __launch_bounds__(128) void k4(const float* __restrict__ inp,
                                          const float* __restrict__ w3,
                                          const float* __restrict__ b3g,
                                          const float* __restrict__ w4,
                                          const float* __restrict__ b4g,
                                          const float* __restrict__ w5,
                                          const float* __restrict__ b5g,
                                          const float* __restrict__ n2wg,
                                          const float* __restrict__ n2bg,
                                          const float* __restrict__ betag,
                                          const float* __restrict__ gammag,
                                          float* __restrict__ out) {
    __shared__ __align__(16) __half2 w3h[32 * 16];  // [o][c2]
    __shared__ __align__(16) __half2 w4h[64 * 16];
    __shared__ __align__(16) __half2 w5h[32 * 16];
    __shared__ float sv[32], n2w[32], n2b[32], bet[32], gam[32];
    __shared__ float b3s[32], b4s[64], b5s[32];

    int tid = threadIdx.x;
    int p = blockIdx.x * 128 + tid;
    int b = p >> 16, pix = p & 65535;

    for (int i = tid; i < 512; i += 128) {
        int o = i >> 4, c2 = i & 15;
        w3h[i] = __floats2half2_rn(w3[o * 32 + 2 * c2], w3[o * 32 + 2 * c2 + 1]);
        w5h[i] = __floats2half2_rn(w5[o * 32 + 2 * c2], w5[o * 32 + 2 * c2 + 1]);
    }
    for (int i = tid; i < 1024; i += 128) {
        int o = i >> 4, c2 = i & 15;
        w4h[i] = __floats2half2_rn(w4[o * 32 + 2 * c2], w4[o * 32 + 2 * c2 + 1]);
    }
    if (tid < 32) {
        sv[tid] = g_s[b * 32 + tid];
        n2w[tid] = n2wg[tid];
        n2b[tid] = n2bg[tid];
        bet[tid] = betag[tid];
        gam[tid] = gammag[tid];
        b3s[tid] = b3g[tid];
        b5s[tid] = b5g[tid];
    }
    if (tid < 64) b4s[tid] = b4g[tid];
    __syncthreads();

    // x = gate_out * s (fp16 load), half2 channel pairs
    __half2 xh[16];
    {
        const __half* xg = g_xsg + b * CC * HW + pix;
#pragma unroll
        for (int c2 = 0; c2 < 16; c2++) {
            float v0 = __half2float(xg[(2 * c2) * HW]) * sv[2 * c2];
            float v1 = __half2float(xg[(2 * c2 + 1) * HW]) * sv[2 * c2 + 1];
            xh[c2] = __floats2half2_rn(v0, v1);
        }
    }

    // ---- conv3 (HFMA2) + residual with beta -> yp (fp32 pairs) ----
    u64 yp[16];
    const float* ip = inp + b * CC * HW + pix;
#pragma unroll 2
    for (int j = 0; j < 16; j++) {
        __half2 a0 = __floats2half2_rn(0.f, 0.f);
        __half2 a1 = a0;
        const __half2* wr0 = &w3h[(2 * j) * 16];
        const __half2* wr1 = &w3h[(2 * j + 1) * 16];
#pragma unroll
        for (int c2 = 0; c2 < 16; c2++) {
            a0 = __hfma2(wr0[c2], xh[c2], a0);
            a1 = __hfma2(wr1[c2], xh[c2], a1);
        }
        float y0 = ip[(2 * j) * HW] + bet[2 * j] * (b3s[2 * j] + hsum2h(a0));
        float y1 =
            ip[(2 * j + 1) * HW] + bet[2 * j + 1] * (b3s[2 * j + 1] + hsum2h(a1));
        yp[j] = pack2(y0, y1);
    }

    // ---- LN2 (f32x2 sums) -> zh (half2) ----
    {
        u64 sa = 0ull, qa = 0ull;
#pragma unroll
        for (int j = 0; j < 16; j++) {
            sa = add2(sa, yp[j]);
            qa = ffma2(yp[j], yp[j], qa);
        }
        float s = hsum2(sa), s2 = hsum2(qa);
        float mu = s * (1.f / 32.f);
        float var = s2 * (1.f / 32.f) - mu * mu;
        float rstd = rsqrtf(var + 1e-6f);
#pragma unroll
        for (int j = 0; j < 16; j++) {
            float2 f = unpack2(yp[j]);
            float z0 = (f.x - mu) * rstd * n2w[2 * j] + n2b[2 * j];
            float z1 = (f.y - mu) * rstd * n2w[2 * j + 1] + n2b[2 * j + 1];
            xh[j] = __floats2half2_rn(z0, z1);
        }
    }

    // ---- conv4 (64 outs, HFMA2) + gate -> gh (half2 pairs) ----
    __half2 gh[16];
#pragma unroll 2
    for (int j = 0; j < 16; j++) {
        __half2 aA = __floats2half2_rn(0.f, 0.f);
        __half2 aB = aA, aC = aA, aD = aA;
        const __half2* wA = &w4h[(2 * j) * 16];
        const __half2* wB = &w4h[(2 * j + 1) * 16];
        const __half2* wC = &w4h[(2 * j + 32) * 16];
        const __half2* wD = &w4h[(2 * j + 33) * 16];
#pragma unroll
        for (int c2 = 0; c2 < 16; c2++) {
            __half2 xv = xh[c2];
            aA = __hfma2(wA[c2], xv, aA);
            aB = __hfma2(wB[c2], xv, aB);
            aC = __hfma2(wC[c2], xv, aC);
            aD = __hfma2(wD[c2], xv, aD);
        }
        float g0 = (b4s[2 * j] + hsum2h(aA)) * (b4s[2 * j + 32] + hsum2h(aC));
        float g1 = (b4s[2 * j + 1] + hsum2h(aB)) * (b4s[2 * j + 33] + hsum2h(aD));
        gh[j] = __floats2half2_rn(g0, g1);
    }

    // ---- conv5 (HFMA2) + final residual with gamma ----
    float* op = out + b * CC * HW + pix;
#pragma unroll 2
    for (int j = 0; j < 16; j++) {
        __half2 a0 = __floats2half2_rn(0.f, 0.f);
        __half2 a1 = a0;
        const __half2* wr0 = &w5h[(2 * j) * 16];
        const __half2* wr1 = &w5h[(2 * j + 1) * 16];
#pragma unroll
        for (int c2 = 0; c2 < 16; c2++) {
            a0 = __hfma2(wr0[c2], gh[c2], a0);
            a1 = __hfma2(wr1[c2], gh[c2], a1);
        }
        float2 f = unpack2(yp[j]);
        op[(2 * j) * HW] = f.x + gam[2 * j] * (b5s[2 * j] + hsum2h(a0));
        op[(2 * j + 1) * HW] =
            f.y + gam[2 * j + 1] * (b5s[2 * j + 1] + hsum2h(a1));
    }
}

extern "C" void kernel_launch(void* const* d_in, const int* in_sizes, int n_in,
                              void* d_out, int out_size) {
    const float* inp     = (const float*)d_in[0];
    const float* w2      = (const float*)d_in[1];
    const float* conv1_w = (const float*)d_in[2];
    const float* conv1_b = (const float*)d_in[3];
    const float* conv3_w = (const float*)d_in[4];
    const float* conv3_b = (const float*)d_in[5];
    const float* sca_w   = (const float*)d_in[6];
    const float* sca_b   = (const float*)d_in[7];
    const float* conv4_w = (const float*)d_in[8];
    const float* conv4_b = (const float*)d_in[9];
    const float* conv5_w = (const float*)d_in[10];
    const float* conv5_b = (const float*)d_in[11];
    const float* norm1_w = (const float*)d_in[12];
    const float* norm1_b = (const float*)d_in[13];
    const float* norm2_w = (const float*)d_in[14];
    const float* norm2_b = (const float*)d_in[15];
    const float* beta    = (const float*)d_in[16];
    const float* gamma   = (const float*)d_in[17];
    float* out = (float*)d_out;

    k1<<<1024, 128>>>(inp, conv1_w, conv1_b, norm1_w, norm1_b);
    k2<<<dim3(64, 32, 4), 128>>>(w2);
    k3<<<1, 128>>>(sca_w, sca_b);
    k4<<<2048, 128>>>(inp, conv3_w, conv3_b, conv4_w, conv4_b, conv5_w, conv5_b,
                      norm2_w, norm2_b, beta, gamma, out);
}

// round 12
// speedup vs baseline: 1.6000x; 1.0179x over previous
#include <cuda_runtime.h>
#include <cuda_fp16.h>

typedef unsigned long long u64;

// Problem constants
#define BB 4
#define CC 32
#define DW 64
#define HH 256
#define WW 256
#define HW 65536

// Scratch (device globals: allocation-free rule). fp16 intermediates.
__device__ __half g_t[BB * DW * HW];    // conv1(LN(inp)) output, 32 MB
__device__ __half g_xsg[BB * CC * HW];  // gate output, 16 MB
__device__ float g_part[BB * CC * 64];  // per-(b,ch,tile) partial sums
__device__ float g_s[BB * CC];          // SCA scale per (b,ch)

// ---- packed fp32x2 helpers (sm_100+) ----
__device__ __forceinline__ u64 pack2(float lo, float hi) {
    u64 r;
    asm("mov.b64 %0, {%1,%2};" : "=l"(r) : "f"(lo), "f"(hi));
    return r;
}
__device__ __forceinline__ float2 unpack2(u64 v) {
    float lo, hi;
    asm("mov.b64 {%0,%1}, %2;" : "=f"(lo), "=f"(hi) : "l"(v));
    return make_float2(lo, hi);
}
__device__ __forceinline__ u64 ffma2(u64 a, u64 b, u64 c) {
    u64 d;
    asm("fma.rn.f32x2 %0, %1, %2, %3;" : "=l"(d) : "l"(a), "l"(b), "l"(c));
    return d;
}
__device__ __forceinline__ u64 add2(u64 a, u64 b) {
    u64 d;
    asm("add.rn.f32x2 %0, %1, %2;" : "=l"(d) : "l"(a), "l"(b));
    return d;
}
__device__ __forceinline__ u64 mul2(u64 a, u64 b) {
    u64 d;
    asm("mul.rn.f32x2 %0, %1, %2;" : "=l"(d) : "l"(a), "l"(b));
    return d;
}
__device__ __forceinline__ float hsum2(u64 v) {
    float2 f = unpack2(v);
    return f.x + f.y;
}
__device__ __forceinline__ float hsum2h(__half2 v) {
    float2 f = __half22float2(v);
    return f.x + f.y;
}

// =====================================================================
// K1: per-pixel LayerNorm(channel) + conv1 (32 -> 64), writes g_t (fp16)
// PIXEL-PAIR version (frozen from R10).
// =====================================================================
__global__ __launch_bounds__(128) void k1(const float* __restrict__ inp,
                                          const float* __restrict__ w1,
                                          const float* __restrict__ b1g,
                                          const float* __restrict__ n1w,
                                          const float* __restrict__ n1b) {
    __shared__ __align__(16) __half2 w1h[64 * 16];  // [o][c2] channel pairs
    __shared__ float snw[32], snb[32], sb64[64];
    int tid = threadIdx.x;
    for (int i = tid; i < 1024; i += 128) {
        int o = i >> 4, c2 = i & 15;
        w1h[i] = __floats2half2_rn(w1[o * 32 + 2 * c2], w1[o * 32 + 2 * c2 + 1]);
    }
    if (tid < 32) { snw[tid] = n1w[tid]; snb[tid] = n1b[tid]; }
    if (tid < 64) sb64[tid] = b1g[tid];
    __syncthreads();

    int p = blockIdx.x * 256 + tid * 2;  // 2 pixels per thread
    int b = p >> 16, pix = p & 65535;
    const float* ip = inp + b * CC * HW + pix;

    u64 xv[32];
    u64 sa = 0ull, qa = 0ull;
#pragma unroll
    for (int c = 0; c < 32; c++) {
        float2 v = *(const float2*)&ip[c * HW];
        u64 t = pack2(v.x, v.y);
        xv[c] = t;
        sa = add2(sa, t);
        qa = ffma2(t, t, qa);
    }
    u64 nmu = mul2(sa, pack2(-1.f / 32.f, -1.f / 32.f));
    float2 qf = unpack2(qa);
    float2 nm = unpack2(nmu);
    float var0 = qf.x * (1.f / 32.f) - nm.x * nm.x;
    float var1 = qf.y * (1.f / 32.f) - nm.y * nm.y;
    u64 rs2 = pack2(rsqrtf(var0 + 1e-6f), rsqrtf(var1 + 1e-6f));

    __half2 xh0[16], xh1[16];
#pragma unroll
    for (int c2 = 0; c2 < 16; c2++) {
        int ca = 2 * c2, cb = 2 * c2 + 1;
        u64 ta = mul2(add2(xv[ca], nmu), rs2);
        u64 tb = mul2(add2(xv[cb], nmu), rs2);
        u64 za = ffma2(ta, pack2(snw[ca], snw[ca]), pack2(snb[ca], snb[ca]));
        u64 zb = ffma2(tb, pack2(snw[cb], snw[cb]), pack2(snb[cb], snb[cb]));
        float2 fa = unpack2(za), fb = unpack2(zb);
        xh0[c2] = __floats2half2_rn(fa.x, fb.x);
        xh1[c2] = __floats2half2_rn(fa.y, fb.y);
    }

    __half* op = g_t + b * DW * HW + pix;
#pragma unroll 4
    for (int o = 0; o < 64; o++) {
        __half2 a0 = __floats2half2_rn(0.f, 0.f);
        __half2 a1 = a0;
        const __half2* wr = &w1h[o * 16];
#pragma unroll
        for (int c2 = 0; c2 < 16; c2++) {
            __half2 w = wr[c2];
            a0 = __hfma2(w, xh0[c2], a0);
            a1 = __hfma2(w, xh1[c2], a1);
        }
        float r0 = sb64[o] + hsum2h(a0);
        float r1 = sb64[o] + hsum2h(a1);
        *(__half2*)&op[o * HW] = __floats2half2_rn(r0, r1);
    }
}

// =====================================================================
// K2: DDF + SimpleGate + SCA partials — HALF2-LANE (frozen from R11).
// =====================================================================
__global__ __launch_bounds__(128) void k2(const float* __restrict__ w2g) {
    int tile = blockIdx.x;  // 0..63
    int chp = blockIdx.y;   // 0..31
    int b = blockIdx.z;
    int tyi = tile >> 3, txi = tile & 7;
    int h0 = tyi * 32, w0 = txi * 32;
    const int TSTR = 35;  // smem row stride in half2 elems

    __shared__ __align__(16) __half2 tin[34 * TSTR];  // (ch0, ch1) per px
    __shared__ __align__(16) __half2 Wc[9][36];       // (ch0, ch1) per wgt
    __shared__ float red[4];

    int tid = threadIdx.x;

    {
        const __half* src0 = g_t + (b * DW + chp) * HW;
        const __half* src1 = g_t + (b * DW + chp + 32) * HW;
        __half hz = __float2half_rn(0.f);
        for (int idx = tid; idx < 34 * 34; idx += 128) {
            int r = idx / 34, c = idx - r * 34;
            int gh = h0 - 1 + r, gw = w0 - 1 + c;
            __half v0 = hz, v1 = hz;
            if ((unsigned)gh < 256u && (unsigned)gw < 256u) {
                int off = gh * 256 + gw;
                v0 = src0[off];
                v1 = src1[off];
            }
            tin[r * TSTR + c] = __halves2half2(v0, v1);
        }
    }
    {
        int ybase = 4 * tyi - 1, xbase = 4 * txi - 1;
        for (int idx = tid; idx < 324; idx += 128) {
            int t = idx / 36;
            int rc = idx - t * 36;
            int rr = rc / 6, cj = rc - rr * 6;
            int ys = min(max(ybase + rr, 0), 31);
            int xs = min(max(xbase + cj, 0), 31);
            float wv0 = w2g[(((b * 64 + chp) * 9 + t) * 32 + ys) * 32 + xs];
            float wv1 = w2g[(((b * 64 + chp + 32) * 9 + t) * 32 + ys) * 32 + xs];
            Wc[t][rc] = __floats2half2_rn(wv0, wv1);
        }
    }
    __syncthreads();

    int row = tid >> 2;        // 0..31
    int seg = (tid & 3) * 8;   // 0,8,16,24
    int h = h0 + row;

    float srcy = (h - 3.5f) * 0.125f;
    float y0f = floorf(srcy);
    float fy = srcy - y0f;
    int y0 = (int)y0f;
    int ybase = 4 * tyi - 1;
    int y0l = max(y0, 0) - ybase;
    int y1l = min(y0 + 1, 31) - ybase;

    int m = 4 * txi + (seg >> 3);
    int xbase = 4 * txi - 1;
    int a0 = max(m - 1, 0) - xbase;
    int a1 = m - xbase;
    int b1i = min(m + 1, 31) - xbase;

    __half2 fy2 = __float2half2_rn(fy);
    const __half2 K0 = __float2half2_rn(0.5625f);
    const __half2 K1 = __float2half2_rn(0.6875f);
    const __half2 K2 = __float2half2_rn(0.8125f);
    const __half2 K3 = __float2half2_rn(0.9375f);
    const __half2 K4 = __float2half2_rn(0.0625f);
    const __half2 K5 = __float2half2_rn(0.1875f);
    const __half2 K6 = __float2half2_rn(0.3125f);
    const __half2 K7 = __float2half2_rn(0.4375f);

    __half2 ra[10], rb[10], rcr[10];
#pragma unroll
    for (int k = 0; k < 10; k++) {
        ra[k] = tin[row * TSTR + seg + k];
        rb[k] = tin[(row + 1) * TSTR + seg + k];
        rcr[k] = tin[(row + 2) * TSTR + seg + k];
    }

    __half2 acc[8];
#pragma unroll
    for (int i = 0; i < 8; i++) acc[i] = __floats2half2_rn(0.f, 0.f);

#define TAP(RR, T, DX)                                                    \
    {                                                                     \
        const __half2* Wp = Wc[T];                                        \
        __half2 v0a = Wp[y0l * 6 + a0], v0b = Wp[y1l * 6 + a0];           \
        __half2 v1a = Wp[y0l * 6 + a1], v1b = Wp[y1l * 6 + a1];           \
        __half2 v2a = Wp[y0l * 6 + b1i], v2b = Wp[y1l * 6 + b1i];         \
        __half2 v0 = __hfma2(fy2, __hsub2(v0b, v0a), v0a);                \
        __half2 v1 = __hfma2(fy2, __hsub2(v1b, v1a), v1a);                \
        __half2 v2 = __hfma2(fy2, __hsub2(v2b, v2a), v2a);                \
        __half2 dA = __hsub2(v1, v0), dB = __hsub2(v2, v1);               \
        acc[0] = __hfma2(__hfma2(K0, dA, v0), RR[0 + DX], acc[0]);        \
        acc[1] = __hfma2(__hfma2(K1, dA, v0), RR[1 + DX], acc[1]);        \
        acc[2] = __hfma2(__hfma2(K2, dA, v0), RR[2 + DX], acc[2]);        \
        acc[3] = __hfma2(__hfma2(K3, dA, v0), RR[3 + DX], acc[3]);        \
        acc[4] = __hfma2(__hfma2(K4, dB, v1), RR[4 + DX], acc[4]);        \
        acc[5] = __hfma2(__hfma2(K5, dB, v1), RR[5 + DX], acc[5]);        \
        acc[6] = __hfma2(__hfma2(K6, dB, v1), RR[6 + DX], acc[6]);        \
        acc[7] = __hfma2(__hfma2(K7, dB, v1), RR[7 + DX], acc[7]);        \
    }
    TAP(ra, 0, 0) TAP(ra, 1, 1) TAP(ra, 2, 2)
    TAP(rb, 3, 0) TAP(rb, 4, 1) TAP(rb, 5, 2)
    TAP(rcr, 6, 0) TAP(rcr, 7, 1) TAP(rcr, 8, 2)
#undef TAP

    float g[8];
    float tsum = 0.f;
#pragma unroll
    for (int i = 0; i < 8; i++) {
        float2 f = __half22float2(acc[i]);
        g[i] = f.x * f.y;
        tsum += g[i];
    }
    __half2* op =
        (__half2*)(g_xsg + (b * CC + chp) * HW + h * 256 + w0 + seg);
    op[0] = __floats2half2_rn(g[0], g[1]);
    op[1] = __floats2half2_rn(g[2], g[3]);
    op[2] = __floats2half2_rn(g[4], g[5]);
    op[3] = __floats2half2_rn(g[6], g[7]);

#pragma unroll
    for (int off = 16; off; off >>= 1)
        tsum += __shfl_xor_sync(0xffffffffu, tsum, off);
    if ((tid & 31) == 0) red[tid >> 5] = tsum;
    __syncthreads();
    if (tid == 0)
        g_part[(b * CC + chp) * 64 + tile] = red[0] + red[1] + red[2] + red[3];
}

// =====================================================================
// K3: deterministic reduction of partials + SCA 1x1 conv -> g_s
// =====================================================================
__global__ void k3(const float* __restrict__ sw, const float* __restrict__ sbias) {
    __shared__ float mean_sm[128];
    int tid = threadIdx.x;  // 128 = 4 batches x 32 channels
    int b = tid >> 5, c = tid & 31;
    float sum = 0.f;
    for (int t = 0; t < 64; t++) sum += g_part[(b * CC + c) * 64 + t];
    mean_sm[tid] = sum * (1.f / 65536.f);
    __syncthreads();
    float acc = sbias[c];
#pragma unroll
    for (int k = 0; k < 32; k++) acc += sw[c * 32 + k] * mean_sm[b * 32 + k];
    g_s[tid] = acc;
}

// =====================================================================
// K4: x*s -> conv3 -> y = inp + beta*x -> LN2 -> conv4 -> gate -> conv5
//     -> out = y + gamma*z.  PIXEL-PAIR: each thread owns 2 adjacent
// pixels; one channel-paired weight LDS feeds both pixels' HFMA2 chains.
// =====================================================================
__global__ __launch_bounds__(128) void k4(const float* __restrict__ inp,
                                          const float* __restrict__ w3,
                                          const float* __restrict__ b3g,
                                          const float* __restrict__ w4,
                                          const float* __restrict__ b4g,
                                          const float* __restrict__ w5,
                                          const float* __restrict__ b5g,
                                          const float* __restrict__ n2wg,
                                          const float* __restrict__ n2bg,
                                          const float* __restrict__ betag,
                                          const float* __restrict__ gammag,
                                          float* __restrict__ out) {
    __shared__ __align__(16) __half2 w3h[32 * 16];  // [o][c2] channel pairs
    __shared__ __align__(16) __half2 w4h[64 * 16];
    __shared__ __align__(16) __half2 w5h[32 * 16];
    __shared__ float sv[32], n2w[32], n2b[32], bet[32], gam[32];
    __shared__ float b3s[32], b4s[64], b5s[32];

    int tid = threadIdx.x;
    int p = blockIdx.x * 256 + tid * 2;  // 2 pixels per thread
    int b = p >> 16, pix = p & 65535;

    for (int i = tid; i < 512; i += 128) {
        int o = i >> 4, c2 = i & 15;
        w3h[i] = __floats2half2_rn(w3[o * 32 + 2 * c2], w3[o * 32 + 2 * c2 + 1]);
        w5h[i] = __floats2half2_rn(w5[o * 32 + 2 * c2], w5[o * 32 + 2 * c2 + 1]);
    }
    for (int i = tid; i < 1024; i += 128) {
        int o = i >> 4, c2 = i & 15;
        w4h[i] = __floats2half2_rn(w4[o * 32 + 2 * c2], w4[o * 32 + 2 * c2 + 1]);
    }
    if (tid < 32) {
        sv[tid] = g_s[b * 32 + tid];
        n2w[tid] = n2wg[tid];
        n2b[tid] = n2bg[tid];
        bet[tid] = betag[tid];
        gam[tid] = gammag[tid];
        b3s[tid] = b3g[tid];
        b5s[tid] = b5g[tid];
    }
    if (tid < 64) b4s[tid] = b4g[tid];
    __syncthreads();

    // x = gate_out * s (fp16 half2 loads: lanes = pixels); repack to
    // channel-paired half2 per pixel.
    __half2 xh0[16], xh1[16];
    {
        const __half* xg = g_xsg + b * CC * HW + pix;
#pragma unroll
        for (int c2 = 0; c2 < 16; c2++) {
            float2 fa = __half22float2(*(const __half2*)&xg[(2 * c2) * HW]);
            float2 fb = __half22float2(*(const __half2*)&xg[(2 * c2 + 1) * HW]);
            float s0 = sv[2 * c2], s1 = sv[2 * c2 + 1];
            xh0[c2] = __floats2half2_rn(fa.x * s0, fb.x * s1);  // pixel 0
            xh1[c2] = __floats2half2_rn(fa.y * s0, fb.y * s1);  // pixel 1
        }
    }

    // ---- conv3 (HFMA2, weights shared across pixels) + residual ----
    u64 yp0[16], yp1[16];  // channel pairs per pixel (fp32)
    const float* ip = inp + b * CC * HW + pix;
#pragma unroll 2
    for (int j = 0; j < 16; j++) {
        __half2 z = __floats2half2_rn(0.f, 0.f);
        __half2 a00 = z, a10 = z, a01 = z, a11 = z;
        const __half2* wr0 = &w3h[(2 * j) * 16];
        const __half2* wr1 = &w3h[(2 * j + 1) * 16];
#pragma unroll
        for (int c2 = 0; c2 < 16; c2++) {
            __half2 w0 = wr0[c2], w1 = wr1[c2];
            a00 = __hfma2(w0, xh0[c2], a00);
            a01 = __hfma2(w0, xh1[c2], a01);
            a10 = __hfma2(w1, xh0[c2], a10);
            a11 = __hfma2(w1, xh1[c2], a11);
        }
        float2 i0 = *(const float2*)&ip[(2 * j) * HW];      // (p0,p1)
        float2 i1 = *(const float2*)&ip[(2 * j + 1) * HW];
        float bt0 = bet[2 * j], bt1 = bet[2 * j + 1];
        float bb0 = b3s[2 * j], bb1 = b3s[2 * j + 1];
        yp0[j] = pack2(i0.x + bt0 * (bb0 + hsum2h(a00)),
                       i1.x + bt1 * (bb1 + hsum2h(a10)));
        yp1[j] = pack2(i0.y + bt0 * (bb0 + hsum2h(a01)),
                       i1.y + bt1 * (bb1 + hsum2h(a11)));
    }

    // ---- LN2 per pixel -> zh (reuse xh regs) ----
    {
        u64 sa0 = 0ull, qa0 = 0ull, sa1 = 0ull, qa1 = 0ull;
#pragma unroll
        for (int j = 0; j < 16; j++) {
            sa0 = add2(sa0, yp0[j]);
            qa0 = ffma2(yp0[j], yp0[j], qa0);
            sa1 = add2(sa1, yp1[j]);
            qa1 = ffma2(yp1[j], yp1[j], qa1);
        }
        float s0 = hsum2(sa0), q0 = hsum2(qa0);
        float s1 = hsum2(sa1), q1 = hsum2(qa1);
        float mu0 = s0 * (1.f / 32.f);
        float mu1 = s1 * (1.f / 32.f);
        float rstd0 = rsqrtf(q0 * (1.f / 32.f) - mu0 * mu0 + 1e-6f);
        float rstd1 = rsqrtf(q1 * (1.f / 32.f) - mu1 * mu1 + 1e-6f);
#pragma unroll
        for (int j = 0; j < 16; j++) {
            float w0 = n2w[2 * j], w1 = n2w[2 * j + 1];
            float c0 = n2b[2 * j], c1 = n2b[2 * j + 1];
            float2 f0 = unpack2(yp0[j]);
            float2 f1 = unpack2(yp1[j]);
            xh0[j] = __floats2half2_rn((f0.x - mu0) * rstd0 * w0 + c0,
                                       (f0.y - mu0) * rstd0 * w1 + c1);
            xh1[j] = __floats2half2_rn((f1.x - mu1) * rstd1 * w0 + c0,
                                       (f1.y - mu1) * rstd1 * w1 + c1);
        }
    }

    // ---- conv4 (64 outs, HFMA2, shared weights) + gate -> gh ----
    __half2 gh0[16], gh1[16];
#pragma unroll 2
    for (int j = 0; j < 16; j++) {
        __half2 z = __floats2half2_rn(0.f, 0.f);
        __half2 aA0 = z, aB0 = z, aC0 = z, aD0 = z;
        __half2 aA1 = z, aB1 = z, aC1 = z, aD1 = z;
        const __half2* wA = &w4h[(2 * j) * 16];
        const __half2* wB = &w4h[(2 * j + 1) * 16];
        const __half2* wC = &w4h[(2 * j + 32) * 16];
        const __half2* wD = &w4h[(2 * j + 33) * 16];
#pragma unroll
        for (int c2 = 0; c2 < 16; c2++) {
            __half2 x0 = xh0[c2], x1 = xh1[c2];
            __half2 wa = wA[c2], wb = wB[c2], wc = wC[c2], wd = wD[c2];
            aA0 = __hfma2(wa, x0, aA0);
            aA1 = __hfma2(wa, x1, aA1);
            aB0 = __hfma2(wb, x0, aB0);
            aB1 = __hfma2(wb, x1, aB1);
            aC0 = __hfma2(wc, x0, aC0);
            aC1 = __hfma2(wc, x1, aC1);
            aD0 = __hfma2(wd, x0, aD0);
            aD1 = __hfma2(wd, x1, aD1);
        }
        float bA = b4s[2 * j], bB = b4s[2 * j + 1];
        float bC = b4s[2 * j + 32], bD = b4s[2 * j + 33];
        gh0[j] = __floats2half2_rn((bA + hsum2h(aA0)) * (bC + hsum2h(aC0)),
                                   (bB + hsum2h(aB0)) * (bD + hsum2h(aD0)));
        gh1[j] = __floats2half2_rn((bA + hsum2h(aA1)) * (bC + hsum2h(aC1)),
                                   (bB + hsum2h(aB1)) * (bD + hsum2h(aD1)));
    }

    // ---- conv5 (HFMA2, shared weights) + final residual ----
    float* op = out + b * CC * HW + pix;
#pragma unroll 2
    for (int j = 0; j < 16; j++) {
        __half2 z = __floats2half2_rn(0.f, 0.f);
        __half2 a00 = z, a10 = z, a01 = z, a11 = z;
        const __half2* wr0 = &w5h[(2 * j) * 16];
        const __half2* wr1 = &w5h[(2 * j + 1) * 16];
#pragma unroll
        for (int c2 = 0; c2 < 16; c2++) {
            __half2 w0 = wr0[c2], w1 = wr1[c2];
            a00 = __hfma2(w0, gh0[c2], a00);
            a01 = __hfma2(w0, gh1[c2], a01);
            a10 = __hfma2(w1, gh0[c2], a10);
            a11 = __hfma2(w1, gh1[c2], a11);
        }
        float gm0 = gam[2 * j], gm1 = gam[2 * j + 1];
        float bb0 = b5s[2 * j], bb1 = b5s[2 * j + 1];
        float2 f0 = unpack2(yp0[j]);  // (ch even, ch odd) pixel 0
        float2 f1 = unpack2(yp1[j]);  // pixel 1
        *(float2*)&op[(2 * j) * HW] =
            make_float2(f0.x + gm0 * (bb0 + hsum2h(a00)),
                        f1.x + gm0 * (bb0 + hsum2h(a01)));
        *(float2*)&op[(2 * j + 1) * HW] =
            make_float2(f0.y + gm1 * (bb1 + hsum2h(a10)),
                        f1.y + gm1 * (bb1 + hsum2h(a11)));
    }
}

extern "C" void kernel_launch(void* const* d_in, const int* in_sizes, int n_in,
                              void* d_out, int out_size) {
    const float* inp     = (const float*)d_in[0];
    const float* w2      = (const float*)d_in[1];
    const float* conv1_w = (const float*)d_in[2];
    const float* conv1_b = (const float*)d_in[3];
    const float* conv3_w = (const float*)d_in[4];
    const float* conv3_b = (const float*)d_in[5];
    const float* sca_w   = (const float*)d_in[6];
    const float* sca_b   = (const float*)d_in[7];
    const float* conv4_w = (const float*)d_in[8];
    const float* conv4_b = (const float*)d_in[9];
    const float* conv5_w = (const float*)d_in[10];
    const float* conv5_b = (const float*)d_in[11];
    const float* norm1_w = (const float*)d_in[12];
    const float* norm1_b = (const float*)d_in[13];
    const float* norm2_w = (const float*)d_in[14];
    const float* norm2_b = (const float*)d_in[15];
    const float* beta    = (const float*)d_in[16];
    const float* gamma   = (const float*)d_in[17];
    float* out = (float*)d_out;

    k1<<<1024, 128>>>(inp, conv1_w, conv1_b, norm1_w, norm1_b);
    k2<<<dim3(64, 32, 4), 128>>>(w2);
    k3<<<1, 128>>>(sca_w, sca_b);
    k4<<<1024, 128>>>(inp, conv3_w, conv3_b, conv4_w, conv4_b, conv5_w, conv5_b,
                      norm2_w, norm2_b, beta, gamma, out);
}